// round 11
// baseline (speedup 1.0000x reference)
#include <cuda_runtime.h>
#include <cuda_fp16.h>
#include <math.h>
#include <stdint.h>

// Problem constants
#define BB 16
#define SS 256
#define DD 1024
#define HP 16
#define DK 64
#define HC 8
#define SK 32
#define EPSV 1e-6f

// ---------------- scratch buffers (static device memory; no allocation) ----------------
__device__ __half g_xp[BB*SS*DD];        // LN_p output fp16 [B,S,D]
__device__ __half g_qkv[3*BB*SS*DD];     // pos qkv fp16      [3,B,S,D]
__device__ float  g_xp2[BB*SS*DD];       // pos attn out      [B,S,D]
__device__ __half g_xt[BB*DD*SS];        // LN_c out (transposed) fp16 [B,D,S]
__device__ __half g_qkvc[3*BB*DD*SS];    // channel qkv fp16  [3,B,D,S]
__device__ __half g_xc[BB*DD*SS];        // channel attn out fp16 [B,D,S]
__device__ __half g_WpT_hi[3*DD*DD];     // Wp transposed [N][K], fp16 hi
__device__ __half g_WpT_lo[3*DD*DD];     // fp16 lo (residual)
__device__ __half g_WcT_hi[4*SS*SS];
__device__ __half g_WcT_lo[4*SS*SS];

// ---------------- helpers ----------------
__device__ __forceinline__ void cp_async16(uint32_t smem, const void* g) {
    asm volatile("cp.async.cg.shared.global [%0], [%1], 16;" :: "r"(smem), "l"(g));
}

__device__ __forceinline__ void mma_f16(float* c, const unsigned* a, const unsigned* b) {
    asm volatile("mma.sync.aligned.m16n8k16.row.col.f32.f16.f16.f32 "
        "{%0,%1,%2,%3}, {%4,%5,%6,%7}, {%8,%9}, {%0,%1,%2,%3};"
        : "+f"(c[0]), "+f"(c[1]), "+f"(c[2]), "+f"(c[3])
        : "r"(a[0]), "r"(a[1]), "r"(a[2]), "r"(a[3]), "r"(b[0]), "r"(b[1]));
}

#define LDM4(r, addr) \
    asm volatile("ldmatrix.sync.aligned.m8n8.x4.shared.b16 {%0,%1,%2,%3}, [%4];" \
        : "=r"((r)[0]), "=r"((r)[1]), "=r"((r)[2]), "=r"((r)[3]) : "r"(addr))

__device__ __forceinline__ uint32_t smem_u32(const void* p) {
    uint32_t a;
    asm("{ .reg .u64 t; cvta.to.shared.u64 t, %1; cvt.u32.u64 %0, t; }" : "=r"(a) : "l"(p));
    return a;
}

__device__ __forceinline__ unsigned packh2(float x, float y) {
    __half2 h = __floats2half2_rn(x, y);
    return *(unsigned*)&h;
}

// ---------------- weight transpose + fp16 hi/lo split ----------------
__global__ void __launch_bounds__(256) split_transpose(const float* __restrict__ W,
                                                       __half* __restrict__ hi,
                                                       __half* __restrict__ lo,
                                                       int K, int N)
{
    __shared__ float t[32][33];
    int bz = blockIdx.z;
    W  += (long)bz * K * N;
    hi += (long)bz * K * N;
    lo += (long)bz * K * N;
    int n0 = blockIdx.x * 32, k0 = blockIdx.y * 32;
    int tx = threadIdx.x & 31, ty = threadIdx.x >> 5;
    #pragma unroll
    for (int j = 0; j < 32; j += 8)
        t[ty + j][tx] = W[(long)(k0 + ty + j) * N + n0 + tx];
    __syncthreads();
    #pragma unroll
    for (int j = 0; j < 32; j += 8) {
        float v = t[tx][ty + j];
        __half h = __float2half_rn(v);
        __half l = __float2half_rn(v - __half2float(h));
        long o = (long)(n0 + ty + j) * K + k0 + tx;
        hi[o] = h; lo[o] = l;
    }
}

// ---------------- LayerNorm over channels -> fp16 ----------------
__global__ void __launch_bounds__(256) ln_p_kernel(const float* __restrict__ x,
                                                   const float* __restrict__ ap,
                                                   const float* __restrict__ bp,
                                                   __half* __restrict__ xo)
{
    long row = blockIdx.x;
    const float* xr = x + row * DD;
    int tid = threadIdx.x;
    float s = 0.f, s2 = 0.f;
    #pragma unroll
    for (int i = tid; i < DD; i += 256) { float v = xr[i]; s += v; s2 += v*v; }
    __shared__ float rs[8], rs2[8];
    #pragma unroll
    for (int o = 16; o; o >>= 1) { s += __shfl_xor_sync(~0u, s, o); s2 += __shfl_xor_sync(~0u, s2, o); }
    if ((tid & 31) == 0) { rs[tid>>5] = s; rs2[tid>>5] = s2; }
    __syncthreads();
    s = 0.f; s2 = 0.f;
    #pragma unroll
    for (int w = 0; w < 8; w++) { s += rs[w]; s2 += rs2[w]; }
    float mean = s * (1.f / DD);
    float var  = (s2 - s * mean) * (1.f / (DD - 1));
    float inv  = 1.f / (sqrtf(var) + EPSV);
    #pragma unroll
    for (int i = tid; i < DD; i += 256) {
        float v = xr[i];
        xo[row * DD + i] = __float2half_rn(ap[i] * (v - mean) * inv + bp[i]);
    }
}

// ---------------- fp16 tensor GEMM: C = A * Bhi^T (+ Blo^T) + bias ----------------
// 3-stage cp.async pipeline. A [M][K] fp16, Bh/Bl [N][K] fp16 (K-major).
// BM=128 BN=64 BK=32, 256 threads, warp grid 4(M) x 2(N), warp tile 32x32.
// Targets 3 CTAs/SM (__launch_bounds__(256,3)). smem rows stride 40 halfs.
// outMode: 0=fp32 C, 1=fp32 fused [B,D,S]->[B,S,D] transpose, 2=fp16 C.
// compLo: 1 = add A*Blo^T compensation (2 MMAs/k16), 0 = hi only.
#define GA_TILE 10240            // A: 128 x 40 halfs
#define GB_TILE 5120             // B: 64 x 40 halfs
#define G_STAGE 20480            // A + Bh + Bl
#define GEMM_SMEM_BYTES (3 * G_STAGE)   // 61440; transpose buffer 64*129*4=33024 fits

__device__ __forceinline__ void gemm_load_chunk(
    uint32_t sbase,
    const __half* __restrict__ A,
    const __half* __restrict__ Bh, const __half* __restrict__ Bl,
    long row0, int col0, int K, int k0, int buf, int tid, int compLo)
{
    uint32_t base = sbase + buf * G_STAGE;
    #pragma unroll
    for (int i = 0; i < 2; i++) {
        int idx = tid + i * 256;
        int r = idx >> 2, sgi = idx & 3;
        cp_async16(base + (uint32_t)(r * 80 + sgi * 16),
                   &A[(row0 + r) * (long)K + k0 + sgi * 8]);
    }
    {
        int r = tid >> 2, sgi = tid & 3;
        uint32_t d = base + GA_TILE + (uint32_t)(r * 80 + sgi * 16);
        long boff = (long)(col0 + r) * K + k0 + sgi * 8;
        cp_async16(d, &Bh[boff]);
        if (compLo) cp_async16(d + GB_TILE, &Bl[boff]);
    }
    asm volatile("cp.async.commit_group;");
}

__global__ void __launch_bounds__(256, 3) gemm_f16(const __half* __restrict__ A,
                                                   const __half* __restrict__ Bh,
                                                   const __half* __restrict__ Bl,
                                                   const float* __restrict__ bias,
                                                   float* __restrict__ C,
                                                   int K, int Ntot,
                                                   long aB, long bB, long biasB, long cB,
                                                   int outMode, int compLo)
{
    extern __shared__ char smem[];
    uint32_t sbase = smem_u32(smem);
    int tid  = threadIdx.x;
    int warp = tid >> 5, lane = tid & 31;
    int wm = warp & 3, wn = warp >> 2;        // 4 x 2 warp grid, tile 32M x 32N
    int g = lane >> 2, t = lane & 3;
    int bz = blockIdx.z;
    A    += (long)bz * aB;
    Bh   += (long)bz * bB;
    Bl   += (long)bz * bB;
    bias += (long)bz * biasB;
    long row0 = (long)blockIdx.y * 128;
    int  col0 = blockIdx.x * 64;

    uint32_t aAddr = sbase +
        (uint32_t)(((wm * 32 + (lane & 7) + ((lane >> 3) & 1) * 8) * 40 + (lane >> 4) * 8) * 2);
    uint32_t bAddr = sbase + GA_TILE +
        (uint32_t)(((wn * 32 + (lane & 7) + ((lane >> 4) & 1) * 8) * 40 + ((lane >> 3) & 1) * 8) * 2);

    float acc[2][4][4];
    #pragma unroll
    for (int mi = 0; mi < 2; mi++)
        #pragma unroll
        for (int ni = 0; ni < 4; ni++)
            #pragma unroll
            for (int r = 0; r < 4; r++) acc[mi][ni][r] = 0.f;

    int NC = K >> 5;
    gemm_load_chunk(sbase, A, Bh, Bl, row0, col0, K, 0, 0, tid, compLo);
    if (NC > 1) gemm_load_chunk(sbase, A, Bh, Bl, row0, col0, K, 32, 1, tid, compLo);

    for (int c = 0; c < NC; c++) {
        int buf = c % 3;
        if (c + 1 < NC) {
            asm volatile("cp.async.wait_group 1;" ::: "memory");
        } else {
            asm volatile("cp.async.wait_group 0;" ::: "memory");
        }
        __syncthreads();
        if (c + 2 < NC)
            gemm_load_chunk(sbase, A, Bh, Bl, row0, col0, K, (c + 2) << 5, (c + 2) % 3, tid, compLo);

        uint32_t bo = buf * G_STAGE;
        #pragma unroll
        for (int ks = 0; ks < 2; ks++) {
            uint32_t ak = aAddr + bo + ks * 32;
            uint32_t bk = bAddr + bo + ks * 32;
            unsigned af[2][4];
            LDM4(af[0], ak);
            LDM4(af[1], ak + 1280);
            unsigned bhf[2][4];
            LDM4(bhf[0], bk);
            LDM4(bhf[1], bk + 1280);
            #pragma unroll
            for (int mi = 0; mi < 2; mi++)
                #pragma unroll
                for (int ni = 0; ni < 4; ni++)
                    mma_f16(acc[mi][ni], af[mi], &bhf[ni >> 1][(ni & 1) * 2]);
            if (compLo) {
                unsigned blf[2][4];
                LDM4(blf[0], bk + GB_TILE);
                LDM4(blf[1], bk + GB_TILE + 1280);
                #pragma unroll
                for (int mi = 0; mi < 2; mi++)
                    #pragma unroll
                    for (int ni = 0; ni < 4; ni++)
                        mma_f16(acc[mi][ni], af[mi], &blf[ni >> 1][(ni & 1) * 2]);
            }
        }
    }

    if (outMode == 0) {
        float* Cf = C + (long)bz * cB;
        #pragma unroll
        for (int mi = 0; mi < 2; mi++) {
            #pragma unroll
            for (int ni = 0; ni < 4; ni++) {
                long r = row0 + wm * 32 + mi * 16 + g;
                int  cc = col0 + wn * 32 + ni * 8 + 2 * t;
                float b0 = bias[cc], b1 = bias[cc + 1];
                *(float2*)&Cf[r * Ntot + cc]       = make_float2(acc[mi][ni][0] + b0, acc[mi][ni][1] + b1);
                *(float2*)&Cf[(r + 8) * Ntot + cc] = make_float2(acc[mi][ni][2] + b0, acc[mi][ni][3] + b1);
            }
        }
    } else if (outMode == 2) {
        __half* Ch = (__half*)C + (long)bz * cB;
        #pragma unroll
        for (int mi = 0; mi < 2; mi++) {
            #pragma unroll
            for (int ni = 0; ni < 4; ni++) {
                long r = row0 + wm * 32 + mi * 16 + g;
                int  cc = col0 + wn * 32 + ni * 8 + 2 * t;
                float b0 = bias[cc], b1 = bias[cc + 1];
                *(__half2*)&Ch[r * Ntot + cc]       = __floats2half2_rn(acc[mi][ni][0] + b0, acc[mi][ni][1] + b1);
                *(__half2*)&Ch[(r + 8) * Ntot + cc] = __floats2half2_rn(acc[mi][ni][2] + b0, acc[mi][ni][3] + b1);
            }
        }
    } else {
        // stage to smem [s][d] (64 x 129 fp32) then write out[b][s][d] coalesced
        __syncthreads();
        float* Ts = (float*)smem;
        int b = (int)(row0 >> 10), d0 = (int)(row0 & 1023);
        #pragma unroll
        for (int mi = 0; mi < 2; mi++) {
            #pragma unroll
            for (int ni = 0; ni < 4; ni++) {
                int rl = wm * 32 + mi * 16 + g;
                int cl = wn * 32 + ni * 8 + 2 * t;
                float b0 = bias[col0 + cl], b1 = bias[col0 + cl + 1];
                Ts[cl * 129 + rl]           = acc[mi][ni][0] + b0;
                Ts[(cl + 1) * 129 + rl]     = acc[mi][ni][1] + b1;
                Ts[cl * 129 + rl + 8]       = acc[mi][ni][2] + b0;
                Ts[(cl + 1) * 129 + rl + 8] = acc[mi][ni][3] + b1;
            }
        }
        __syncthreads();
        #pragma unroll
        for (int j = 0; j < 8; j++) {
            int sl = j * 8 + (tid >> 5);
            int d4 = (tid & 31) * 4;
            float4 o = make_float4(Ts[sl * 129 + d4], Ts[sl * 129 + d4 + 1],
                                   Ts[sl * 129 + d4 + 2], Ts[sl * 129 + d4 + 3]);
            *(float4*)&C[((long)(b * SS + col0 + sl)) * DD + d0 + d4] = o;
        }
    }
}

// ---------------- positional attention via fp16 tensor cores ----------------
// Qs [128][72] fp16, Ks [256][72] fp16, Vt [64][266] fp16 (V transposed, pad 266)
#define PA_SMEM_BYTES ((128*72 + 256*72 + 64*266) * 2)
__global__ void __launch_bounds__(256) pos_attn_mma(const __half* __restrict__ qkv,
                                                    float* __restrict__ out)
{
    extern __shared__ __half smh[];
    __half* Qs = smh;                 // [128][72]
    __half* Ks = Qs + 128 * 72;       // [256][72]
    __half* Vt = Ks + 256 * 72;       // [64][266]
    int tid = threadIdx.x, lane = tid & 31, w = tid >> 5;
    int qt = blockIdx.x, bh = blockIdx.y;
    int b = bh >> 4, h = bh & 15;

    const __half* Qg = qkv + ((long)b * SS + qt * 128) * DD + h * DK;
    const __half* Kg = qkv + (long)BB*SS*DD + (long)b * SS * DD + h * DK;
    const __half* Vg = Kg + (long)BB*SS*DD;

    for (int idx = tid; idx < 128 * 8; idx += 256) {
        int r = idx >> 3, c = (idx & 7) * 8;
        *(uint4*)&Qs[r * 72 + c] = *(const uint4*)&Qg[(long)r * DD + c];
    }
    for (int idx = tid; idx < 256 * 8; idx += 256) {
        int r = idx >> 3, c = (idx & 7) * 8;
        *(uint4*)&Ks[r * 72 + c] = *(const uint4*)&Kg[(long)r * DD + c];
        uint4 vv = *(const uint4*)&Vg[(long)r * DD + c];
        const __half* vh = (const __half*)&vv;
        #pragma unroll
        for (int j = 0; j < 8; j++) Vt[(c + j) * 266 + r] = vh[j];
    }
    __syncthreads();

    int g = lane >> 2, tig = lane & 3;
    int row = w * 16 + g;

    unsigned qa[4][4];
    #pragma unroll
    for (int ks = 0; ks < 4; ks++) {
        const __half* qb = Qs + row * 72 + ks * 16 + 2 * tig;
        qa[ks][0] = *(const unsigned*)qb;
        qa[ks][1] = *(const unsigned*)(qb + 8 * 72);
        qa[ks][2] = *(const unsigned*)(qb + 8);
        qa[ks][3] = *(const unsigned*)(qb + 8 * 72 + 8);
    }

    float sc[32][4];
    #pragma unroll
    for (int nf = 0; nf < 32; nf++) {
        sc[nf][0] = sc[nf][1] = sc[nf][2] = sc[nf][3] = 0.f;
        const __half* kb = Ks + (nf * 8 + g) * 72 + 2 * tig;
        #pragma unroll
        for (int ks = 0; ks < 4; ks++) {
            unsigned bb[2];
            bb[0] = *(const unsigned*)(kb + ks * 16);
            bb[1] = *(const unsigned*)(kb + ks * 16 + 8);
            mma_f16(sc[nf], qa[ks], bb);
        }
    }

    float mx0 = -1e30f, mx1 = -1e30f;
    #pragma unroll
    for (int nf = 0; nf < 32; nf++) {
        mx0 = fmaxf(mx0, fmaxf(sc[nf][0], sc[nf][1]));
        mx1 = fmaxf(mx1, fmaxf(sc[nf][2], sc[nf][3]));
    }
    mx0 = fmaxf(mx0, __shfl_xor_sync(~0u, mx0, 1));
    mx0 = fmaxf(mx0, __shfl_xor_sync(~0u, mx0, 2));
    mx1 = fmaxf(mx1, __shfl_xor_sync(~0u, mx1, 1));
    mx1 = fmaxf(mx1, __shfl_xor_sync(~0u, mx1, 2));
    float sum0 = 0.f, sum1 = 0.f;
    #pragma unroll
    for (int nf = 0; nf < 32; nf++) {
        float p0 = __expf((sc[nf][0] - mx0) * 0.125f), p1 = __expf((sc[nf][1] - mx0) * 0.125f);
        float p2 = __expf((sc[nf][2] - mx1) * 0.125f), p3 = __expf((sc[nf][3] - mx1) * 0.125f);
        sum0 += p0 + p1; sum1 += p2 + p3;
        sc[nf][0] = p0; sc[nf][1] = p1; sc[nf][2] = p2; sc[nf][3] = p3;
    }
    sum0 += __shfl_xor_sync(~0u, sum0, 1); sum0 += __shfl_xor_sync(~0u, sum0, 2);
    sum1 += __shfl_xor_sync(~0u, sum1, 1); sum1 += __shfl_xor_sync(~0u, sum1, 2);

    #pragma unroll
    for (int ksi = 0; ksi < 16; ksi++) {
        unsigned p0 = packh2(sc[2*ksi][0],   sc[2*ksi][1]);
        unsigned p1 = packh2(sc[2*ksi][2],   sc[2*ksi][3]);
        unsigned p2 = packh2(sc[2*ksi+1][0], sc[2*ksi+1][1]);
        unsigned p3 = packh2(sc[2*ksi+1][2], sc[2*ksi+1][3]);
        unsigned* d = (unsigned*)sc[2*ksi];
        d[0] = p0; d[1] = p1; d[2] = p2; d[3] = p3;
    }

    float o[8][4];
    #pragma unroll
    for (int nf = 0; nf < 8; nf++) { o[nf][0]=o[nf][1]=o[nf][2]=o[nf][3]=0.f; }
    #pragma unroll
    for (int nf = 0; nf < 8; nf++) {
        const __half* vb = Vt + (nf * 8 + g) * 266 + 2 * tig;
        #pragma unroll
        for (int ksi = 0; ksi < 16; ksi++) {
            unsigned bb[2];
            bb[0] = *(const unsigned*)(vb + ksi * 16);
            bb[1] = *(const unsigned*)(vb + ksi * 16 + 8);
            mma_f16(o[nf], (const unsigned*)sc[2*ksi], bb);
        }
    }

    float inv0 = 1.f / sum0, inv1 = 1.f / sum1;
    long orow0 = ((long)b * SS + qt * 128 + row) * DD + h * DK;
    long orow1 = orow0 + 8L * DD;
    #pragma unroll
    for (int nf = 0; nf < 8; nf++) {
        int c = nf * 8 + 2 * tig;
        *(float2*)&out[orow0 + c] = make_float2(o[nf][0] * inv0, o[nf][1] * inv0);
        *(float2*)&out[orow1 + c] = make_float2(o[nf][2] * inv1, o[nf][3] * inv1);
    }
}

// ---------------- LayerNorm over sequence + transpose -> fp16 [B,D,S] ----------------
__global__ void __launch_bounds__(256) ln_c_kernel(const float* __restrict__ xin,
                                                   const float* __restrict__ ac,
                                                   const float* __restrict__ bcv,
                                                   __half* __restrict__ xo)
{
    __shared__ float tile[32][257];
    __shared__ float red[8][32], red2[8][32];
    __shared__ float s_mean[32], s_inv[32];
    int b = blockIdx.y, d0 = blockIdx.x * 32;
    int tid = threadIdx.x, lane = tid & 31, w = tid >> 5;
    const float* base = xin + (long)b * SS * DD + d0;
    #pragma unroll 4
    for (int i = 0; i < 32; i++) {
        int s = w * 32 + i;
        tile[lane][s] = base[(long)s * DD + lane];
    }
    __syncthreads();
    {
        int d = tid & 31, ch = tid >> 5;
        float s1 = 0.f, s2 = 0.f;
        #pragma unroll
        for (int j = 0; j < 32; j++) {
            float v = tile[d][ch * 32 + j]; s1 += v; s2 += v * v;
        }
        red[ch][d] = s1; red2[ch][d] = s2;
    }
    __syncthreads();
    if (tid < 32) {
        float s1 = 0.f, s2 = 0.f;
        #pragma unroll
        for (int ch = 0; ch < 8; ch++) { s1 += red[ch][tid]; s2 += red2[ch][tid]; }
        float mean = s1 * (1.f / SS);
        float var  = (s2 - s1 * mean) * (1.f / (SS - 1));
        s_mean[tid] = mean;
        s_inv[tid]  = 1.f / (sqrtf(var) + EPSV);
    }
    __syncthreads();
    {
        int d = tid >> 3, s0 = (tid & 7) * 32;
        float mean = s_mean[d], inv = s_inv[d];
        long dstBase = ((long)b * DD + d0 + d) * SS;
        #pragma unroll
        for (int j = 0; j < 32; j += 2) {
            int s = s0 + j;
            float v0 = ac[s+0] * (tile[d][s+0] - mean) * inv + bcv[s+0];
            float v1 = ac[s+1] * (tile[d][s+1] - mean) * inv + bcv[s+1];
            *(__half2*)&xo[dstBase + s] = __floats2half2_rn(v0, v1);
        }
    }
}

// ---------------- channel attention via fp16 tensor cores (flash) ----------------
// Qs [128][40], Ks [128][40], Vt [32][138] fp16
#define CA_SMEM_BYTES ((128*40 + 128*40 + 32*138) * 2)
__global__ void __launch_bounds__(256) chan_attn_mma(const __half* __restrict__ qkvc,
                                                     __half* __restrict__ xc)
{
    extern __shared__ __half smh[];
    __half* Qs = smh;                // [128][40]
    __half* Ks = Qs + 128 * 40;
    __half* Vt = Ks + 128 * 40;      // [32][138]
    int tid = threadIdx.x, lane = tid & 31, w = tid >> 5;
    int qt = blockIdx.x, bh = blockIdx.y;
    int b = bh >> 3, h = bh & 7;
    const float scale = 0.1767766952966369f;   // 1/sqrt(32)

    const long qBase = (long)b * DD * SS + h * SK;
    const long nStride = (long)BB * DD * SS;

    for (int idx = tid; idx < 128 * 4; idx += 256) {
        int r = idx >> 2, c = (idx & 3) * 8;
        *(uint4*)&Qs[r * 40 + c] = *(const uint4*)&qkvc[qBase + (long)(qt * 128 + r) * SS + c];
    }
    __syncthreads();

    int g = lane >> 2, tig = lane & 3;
    int row = w * 16 + g;

    unsigned qa[2][4];
    #pragma unroll
    for (int ks = 0; ks < 2; ks++) {
        const __half* qb = Qs + row * 40 + ks * 16 + 2 * tig;
        qa[ks][0] = *(const unsigned*)qb;
        qa[ks][1] = *(const unsigned*)(qb + 8 * 40);
        qa[ks][2] = *(const unsigned*)(qb + 8);
        qa[ks][3] = *(const unsigned*)(qb + 8 * 40 + 8);
    }

    float m0 = -1e30f, m1 = -1e30f, l0 = 0.f, l1 = 0.f;
    float o[4][4];
    #pragma unroll
    for (int nf = 0; nf < 4; nf++) { o[nf][0]=o[nf][1]=o[nf][2]=o[nf][3]=0.f; }

    for (int st = 0; st < 8; st++) {
        __syncthreads();
        for (int idx = tid; idx < 128 * 4; idx += 256) {
            int r = idx >> 2, c = (idx & 3) * 8;
            *(uint4*)&Ks[r * 40 + c] = *(const uint4*)&qkvc[qBase + nStride + (long)(st * 128 + r) * SS + c];
            uint4 vv = *(const uint4*)&qkvc[qBase + 2 * nStride + (long)(st * 128 + r) * SS + c];
            const __half* vh = (const __half*)&vv;
            #pragma unroll
            for (int j = 0; j < 8; j++) Vt[(c + j) * 138 + r] = vh[j];
        }
        __syncthreads();

        float sc[16][4];
        #pragma unroll
        for (int nf = 0; nf < 16; nf++) {
            sc[nf][0] = sc[nf][1] = sc[nf][2] = sc[nf][3] = 0.f;
            const __half* kb = Ks + (nf * 8 + g) * 40 + 2 * tig;
            #pragma unroll
            for (int ks = 0; ks < 2; ks++) {
                unsigned bb[2];
                bb[0] = *(const unsigned*)(kb + ks * 16);
                bb[1] = *(const unsigned*)(kb + ks * 16 + 8);
                mma_f16(sc[nf], qa[ks], bb);
            }
        }
        float tm0 = -1e30f, tm1 = -1e30f;
        #pragma unroll
        for (int nf = 0; nf < 16; nf++) {
            tm0 = fmaxf(tm0, fmaxf(sc[nf][0], sc[nf][1]));
            tm1 = fmaxf(tm1, fmaxf(sc[nf][2], sc[nf][3]));
        }
        tm0 = fmaxf(tm0, __shfl_xor_sync(~0u, tm0, 1));
        tm0 = fmaxf(tm0, __shfl_xor_sync(~0u, tm0, 2));
        tm1 = fmaxf(tm1, __shfl_xor_sync(~0u, tm1, 1));
        tm1 = fmaxf(tm1, __shfl_xor_sync(~0u, tm1, 2));
        float nm0 = fmaxf(m0, tm0), nm1 = fmaxf(m1, tm1);
        float al0 = __expf((m0 - nm0) * scale), al1 = __expf((m1 - nm1) * scale);
        m0 = nm0; m1 = nm1;
        float ts0 = 0.f, ts1 = 0.f;
        #pragma unroll
        for (int nf = 0; nf < 16; nf++) {
            float p0 = __expf((sc[nf][0] - nm0) * scale), p1 = __expf((sc[nf][1] - nm0) * scale);
            float p2 = __expf((sc[nf][2] - nm1) * scale), p3 = __expf((sc[nf][3] - nm1) * scale);
            ts0 += p0 + p1; ts1 += p2 + p3;
            sc[nf][0] = p0; sc[nf][1] = p1; sc[nf][2] = p2; sc[nf][3] = p3;
        }
        ts0 += __shfl_xor_sync(~0u, ts0, 1); ts0 += __shfl_xor_sync(~0u, ts0, 2);
        ts1 += __shfl_xor_sync(~0u, ts1, 1); ts1 += __shfl_xor_sync(~0u, ts1, 2);
        l0 = l0 * al0 + ts0; l1 = l1 * al1 + ts1;
        #pragma unroll
        for (int nf = 0; nf < 4; nf++) {
            o[nf][0] *= al0; o[nf][1] *= al0;
            o[nf][2] *= al1; o[nf][3] *= al1;
        }
        #pragma unroll
        for (int ksi = 0; ksi < 8; ksi++) {
            unsigned p0 = packh2(sc[2*ksi][0],   sc[2*ksi][1]);
            unsigned p1 = packh2(sc[2*ksi][2],   sc[2*ksi][3]);
            unsigned p2 = packh2(sc[2*ksi+1][0], sc[2*ksi+1][1]);
            unsigned p3 = packh2(sc[2*ksi+1][2], sc[2*ksi+1][3]);
            unsigned* d = (unsigned*)sc[2*ksi];
            d[0] = p0; d[1] = p1; d[2] = p2; d[3] = p3;
        }
        #pragma unroll
        for (int nf = 0; nf < 4; nf++) {
            const __half* vb = Vt + (nf * 8 + g) * 138 + 2 * tig;
            #pragma unroll
            for (int ksi = 0; ksi < 8; ksi++) {
                unsigned bb[2];
                bb[0] = *(const unsigned*)(vb + ksi * 16);
                bb[1] = *(const unsigned*)(vb + ksi * 16 + 8);
                mma_f16(o[nf], (const unsigned*)sc[2*ksi], bb);
            }
        }
    }

    float inv0 = 1.f / l0, inv1 = 1.f / l1;
    long orow0 = ((long)b * DD + qt * 128 + row) * SS + h * SK;
    long orow1 = orow0 + 8L * SS;
    #pragma unroll
    for (int nf = 0; nf < 4; nf++) {
        int c = nf * 8 + 2 * tig;
        *(__half2*)&xc[orow0 + c] = __floats2half2_rn(o[nf][0] * inv0, o[nf][1] * inv0);
        *(__half2*)&xc[orow1 + c] = __floats2half2_rn(o[nf][2] * inv1, o[nf][3] * inv1);
    }
}

// ---------------- launch ----------------
extern "C" void kernel_launch(void* const* d_in, const int* in_sizes, int n_in,
                              void* d_out, int out_size)
{
    const float* x   = (const float*)d_in[0];
    const float* Wp  = (const float*)d_in[1];
    const float* bp  = (const float*)d_in[2];
    const float* Wc  = (const float*)d_in[3];
    const float* bc  = (const float*)d_in[4];
    const float* ap  = (const float*)d_in[5];
    const float* bpp = (const float*)d_in[6];
    const float* ac  = (const float*)d_in[7];
    const float* bcc = (const float*)d_in[8];
    float* out = (float*)d_out;

    void *p_xp, *p_qkv, *p_xp2, *p_xt, *p_qkvc, *p_xc;
    void *p_wph, *p_wpl, *p_wch, *p_wcl;
    cudaGetSymbolAddress(&p_xp, g_xp);
    cudaGetSymbolAddress(&p_qkv, g_qkv);
    cudaGetSymbolAddress(&p_xp2, g_xp2);
    cudaGetSymbolAddress(&p_xt, g_xt);
    cudaGetSymbolAddress(&p_qkvc, g_qkvc);
    cudaGetSymbolAddress(&p_xc, g_xc);
    cudaGetSymbolAddress(&p_wph, g_WpT_hi);
    cudaGetSymbolAddress(&p_wpl, g_WpT_lo);
    cudaGetSymbolAddress(&p_wch, g_WcT_hi);
    cudaGetSymbolAddress(&p_wcl, g_WcT_lo);
    __half* xp   = (__half*)p_xp;
    __half* qkv  = (__half*)p_qkv;
    float* xp2   = (float*)p_xp2;
    __half* xt   = (__half*)p_xt;
    __half* qkvc = (__half*)p_qkvc;
    __half* xc   = (__half*)p_xc;
    __half* WpTh = (__half*)p_wph;
    __half* WpTl = (__half*)p_wpl;
    __half* WcTh = (__half*)p_wch;
    __half* WcTl = (__half*)p_wcl;

    cudaFuncSetAttribute((const void*)pos_attn_mma,  cudaFuncAttributeMaxDynamicSharedMemorySize, PA_SMEM_BYTES);
    cudaFuncSetAttribute((const void*)chan_attn_mma, cudaFuncAttributeMaxDynamicSharedMemorySize, CA_SMEM_BYTES);
    cudaFuncSetAttribute((const void*)gemm_f16,      cudaFuncAttributeMaxDynamicSharedMemorySize, GEMM_SMEM_BYTES);

    // 0. transpose + fp16 hi/lo split of weights
    split_transpose<<<dim3(DD/32, DD/32, 3), 256>>>(Wp, WpTh, WpTl, DD, DD);
    split_transpose<<<dim3(SS/32, SS/32, 4), 256>>>(Wc, WcTh, WcTl, SS, SS);

    // 1. LayerNorm over D -> fp16
    ln_p_kernel<<<BB*SS, 256>>>(x, ap, bpp, xp);

    // 2. positional qkv (fp16, hi-only weights) -> fp16 qkv
    gemm_f16<<<dim3(DD/64, (BB*SS)/128, 3), 256, GEMM_SMEM_BYTES>>>(
        xp, WpTh, WpTl, bp, (float*)qkv, DD, DD,
        0L, (long)DD*DD, (long)DD, (long)BB*SS*DD, 2, 0);

    // 3. positional attention (fp16 tensor cores)
    pos_attn_mma<<<dim3(2, BB*HP), 256, PA_SMEM_BYTES>>>(qkv, xp2);

    // 4. LayerNorm over S + transpose -> fp16 [B,D,S]
    ln_c_kernel<<<dim3(DD/32, BB), 256>>>(xp2, ac, bcc, xt);

    // 5. channel qkv (fp16 hi+lo compensated) -> fp16 qkvc
    gemm_f16<<<dim3(SS/64, (BB*DD)/128, 3), 256, GEMM_SMEM_BYTES>>>(
        xt, WcTh, WcTl, bc, (float*)qkvc, SS, SS,
        0L, (long)SS*SS, (long)SS, (long)BB*DD*SS, 2, 1);

    // 6. channel attention (fp16 tensor cores, flash) -> fp16
    chan_attn_mma<<<dim3(8, BB*HC), 256, CA_SMEM_BYTES>>>(qkvc, xc);

    // 7. output projection (fp16 hi+lo compensated) with Wc[3], bc[3]; fused transpose -> out
    gemm_f16<<<dim3(SS/64, (BB*DD)/128, 1), 256, GEMM_SMEM_BYTES>>>(
        xc, WcTh + 3L*SS*SS, WcTl + 3L*SS*SS, bc + 3L*SS, out, SS, SS,
        0L, 0L, 0L, 0L, 1, 1);
}

// round 12
// speedup vs baseline: 1.0597x; 1.0597x over previous
#include <cuda_runtime.h>
#include <cuda_fp16.h>
#include <math.h>
#include <stdint.h>

// Problem constants
#define BB 16
#define SS 256
#define DD 1024
#define HP 16
#define DK 64
#define HC 8
#define SK 32
#define EPSV 1e-6f

// ---------------- scratch buffers (static device memory; no allocation) ----------------
__device__ __half g_xp[BB*SS*DD];        // LN_p output fp16 [B,S,D]
__device__ __half g_qkv[3*BB*SS*DD];     // pos qkv fp16      [3,B,S,D]
__device__ float  g_xp2[BB*SS*DD];       // pos attn out      [B,S,D]
__device__ __half g_xt[BB*DD*SS];        // LN_c out (transposed) fp16 [B,D,S]
__device__ __half g_qkvc[3*BB*DD*SS];    // channel qkv fp16  [3,B,D,S]
__device__ __half g_xc[BB*DD*SS];        // channel attn out fp16 [B,D,S]
__device__ __half g_WpT_hi[3*DD*DD];     // Wp transposed [N][K], fp16 hi
__device__ __half g_WpT_lo[3*DD*DD];     // fp16 lo (residual)
__device__ __half g_WcT_hi[4*SS*SS];
__device__ __half g_WcT_lo[4*SS*SS];

// ---------------- helpers ----------------
__device__ __forceinline__ void cp_async16(uint32_t smem, const void* g) {
    asm volatile("cp.async.cg.shared.global [%0], [%1], 16;" :: "r"(smem), "l"(g));
}

__device__ __forceinline__ void mma_f16(float* c, const unsigned* a, const unsigned* b) {
    asm volatile("mma.sync.aligned.m16n8k16.row.col.f32.f16.f16.f32 "
        "{%0,%1,%2,%3}, {%4,%5,%6,%7}, {%8,%9}, {%0,%1,%2,%3};"
        : "+f"(c[0]), "+f"(c[1]), "+f"(c[2]), "+f"(c[3])
        : "r"(a[0]), "r"(a[1]), "r"(a[2]), "r"(a[3]), "r"(b[0]), "r"(b[1]));
}

#define LDM4(r, addr) \
    asm volatile("ldmatrix.sync.aligned.m8n8.x4.shared.b16 {%0,%1,%2,%3}, [%4];" \
        : "=r"((r)[0]), "=r"((r)[1]), "=r"((r)[2]), "=r"((r)[3]) : "r"(addr))

__device__ __forceinline__ uint32_t smem_u32(const void* p) {
    uint32_t a;
    asm("{ .reg .u64 t; cvta.to.shared.u64 t, %1; cvt.u32.u64 %0, t; }" : "=r"(a) : "l"(p));
    return a;
}

__device__ __forceinline__ unsigned packh2(float x, float y) {
    __half2 h = __floats2half2_rn(x, y);
    return *(unsigned*)&h;
}

// ---------------- weight transpose + fp16 hi/lo split ----------------
__global__ void __launch_bounds__(256) split_transpose(const float* __restrict__ W,
                                                       __half* __restrict__ hi,
                                                       __half* __restrict__ lo,
                                                       int K, int N)
{
    __shared__ float t[32][33];
    int bz = blockIdx.z;
    W  += (long)bz * K * N;
    hi += (long)bz * K * N;
    lo += (long)bz * K * N;
    int n0 = blockIdx.x * 32, k0 = blockIdx.y * 32;
    int tx = threadIdx.x & 31, ty = threadIdx.x >> 5;
    #pragma unroll
    for (int j = 0; j < 32; j += 8)
        t[ty + j][tx] = W[(long)(k0 + ty + j) * N + n0 + tx];
    __syncthreads();
    #pragma unroll
    for (int j = 0; j < 32; j += 8) {
        float v = t[tx][ty + j];
        __half h = __float2half_rn(v);
        __half l = __float2half_rn(v - __half2float(h));
        long o = (long)(n0 + ty + j) * K + k0 + tx;
        hi[o] = h; lo[o] = l;
    }
}

// ---------------- LayerNorm over channels -> fp16 ----------------
__global__ void __launch_bounds__(256) ln_p_kernel(const float* __restrict__ x,
                                                   const float* __restrict__ ap,
                                                   const float* __restrict__ bp,
                                                   __half* __restrict__ xo)
{
    long row = blockIdx.x;
    const float* xr = x + row * DD;
    int tid = threadIdx.x;
    float s = 0.f, s2 = 0.f;
    #pragma unroll
    for (int i = tid; i < DD; i += 256) { float v = xr[i]; s += v; s2 += v*v; }
    __shared__ float rs[8], rs2[8];
    #pragma unroll
    for (int o = 16; o; o >>= 1) { s += __shfl_xor_sync(~0u, s, o); s2 += __shfl_xor_sync(~0u, s2, o); }
    if ((tid & 31) == 0) { rs[tid>>5] = s; rs2[tid>>5] = s2; }
    __syncthreads();
    s = 0.f; s2 = 0.f;
    #pragma unroll
    for (int w = 0; w < 8; w++) { s += rs[w]; s2 += rs2[w]; }
    float mean = s * (1.f / DD);
    float var  = (s2 - s * mean) * (1.f / (DD - 1));
    float inv  = 1.f / (sqrtf(var) + EPSV);
    #pragma unroll
    for (int i = tid; i < DD; i += 256) {
        float v = xr[i];
        xo[row * DD + i] = __float2half_rn(ap[i] * (v - mean) * inv + bp[i]);
    }
}

// ---------------- fp16 tensor GEMM: C = A * Bhi^T (+ Blo^T) + bias ----------------
// 3-stage cp.async pipeline. A [M][K] fp16, Bh/Bl [N][K] fp16 (K-major).
// BM=128 BN=128 BK=32, 256 threads. Warp grid 2(M) x 4(N), warp tile 64x32.
// smem rows stride 40 halfs. outMode: 0=fp32 C, 1=fp32 fused transpose, 2=fp16 C.
// compLo: 1 = add A*Blo^T compensation term, 0 = hi only.
#define GT_TILE 10240
#define GEMM_SMEM_BYTES (9 * GT_TILE)   // 92160; transpose buffer (66048) fits

__device__ __forceinline__ void gemm_load_chunk(
    uint32_t sbase,
    const __half* __restrict__ A,
    const __half* __restrict__ Bh, const __half* __restrict__ Bl,
    long row0, int col0, int K, int k0, int buf, int tid, int compLo)
{
    uint32_t base = sbase + buf * 3 * GT_TILE;
    #pragma unroll
    for (int i = 0; i < 2; i++) {
        int idx = tid + i * 256;
        int r = idx >> 2, sgi = idx & 3;
        uint32_t d = base + (uint32_t)(r * 80 + sgi * 16);
        long aoff = (row0 + r) * (long)K + k0 + sgi * 8;
        long boff = (long)(col0 + r) * K + k0 + sgi * 8;
        cp_async16(d,               &A[aoff]);
        cp_async16(d + GT_TILE,     &Bh[boff]);
        if (compLo) cp_async16(d + 2*GT_TILE, &Bl[boff]);
    }
    asm volatile("cp.async.commit_group;");
}

__global__ void __launch_bounds__(256, 2) gemm_f16(const __half* __restrict__ A,
                                                   const __half* __restrict__ Bh,
                                                   const __half* __restrict__ Bl,
                                                   const float* __restrict__ bias,
                                                   float* __restrict__ C,
                                                   int K, int Ntot,
                                                   long aB, long bB, long biasB, long cB,
                                                   int outMode, int compLo)
{
    extern __shared__ char smem[];
    uint32_t sbase = smem_u32(smem);
    int tid  = threadIdx.x;
    int warp = tid >> 5, lane = tid & 31;
    int wm = warp & 1, wn = warp >> 1;        // 2 x 4 warp grid, tile 64M x 32N
    int g = lane >> 2, t = lane & 3;
    int bz = blockIdx.z;
    A    += (long)bz * aB;
    Bh   += (long)bz * bB;
    Bl   += (long)bz * bB;
    bias += (long)bz * biasB;
    long row0 = (long)blockIdx.y * 128;
    int  col0 = blockIdx.x * 128;

    uint32_t aAddr = sbase +
        (uint32_t)(((wm * 64 + (lane & 7) + ((lane >> 3) & 1) * 8) * 40 + (lane >> 4) * 8) * 2);
    uint32_t bAddr = sbase + GT_TILE +
        (uint32_t)(((wn * 32 + (lane & 7) + ((lane >> 4) & 1) * 8) * 40 + ((lane >> 3) & 1) * 8) * 2);

    float acc[4][4][4];
    #pragma unroll
    for (int mi = 0; mi < 4; mi++)
        #pragma unroll
        for (int ni = 0; ni < 4; ni++)
            #pragma unroll
            for (int r = 0; r < 4; r++) acc[mi][ni][r] = 0.f;

    int NC = K >> 5;
    gemm_load_chunk(sbase, A, Bh, Bl, row0, col0, K, 0, 0, tid, compLo);
    if (NC > 1) gemm_load_chunk(sbase, A, Bh, Bl, row0, col0, K, 32, 1, tid, compLo);

    for (int c = 0; c < NC; c++) {
        int buf = c % 3;
        if (c + 1 < NC) {
            asm volatile("cp.async.wait_group 1;" ::: "memory");
        } else {
            asm volatile("cp.async.wait_group 0;" ::: "memory");
        }
        __syncthreads();
        if (c + 2 < NC)
            gemm_load_chunk(sbase, A, Bh, Bl, row0, col0, K, (c + 2) << 5, (c + 2) % 3, tid, compLo);

        uint32_t bo = buf * 3 * GT_TILE;
        #pragma unroll
        for (int ks = 0; ks < 2; ks++) {
            uint32_t ak = aAddr + bo + ks * 32;
            uint32_t bk = bAddr + bo + ks * 32;
            unsigned af[4][4];
            LDM4(af[0], ak);
            LDM4(af[1], ak + 1280);
            LDM4(af[2], ak + 2560);
            LDM4(af[3], ak + 3840);
            unsigned bhf[2][4];
            LDM4(bhf[0], bk);
            LDM4(bhf[1], bk + 1280);
            #pragma unroll
            for (int mi = 0; mi < 4; mi++)
                #pragma unroll
                for (int ni = 0; ni < 4; ni++)
                    mma_f16(acc[mi][ni], af[mi], &bhf[ni >> 1][(ni & 1) * 2]);
            if (compLo) {
                unsigned blf[2][4];
                LDM4(blf[0], bk + GT_TILE);
                LDM4(blf[1], bk + GT_TILE + 1280);
                #pragma unroll
                for (int mi = 0; mi < 4; mi++)
                    #pragma unroll
                    for (int ni = 0; ni < 4; ni++)
                        mma_f16(acc[mi][ni], af[mi], &blf[ni >> 1][(ni & 1) * 2]);
            }
        }
    }

    if (outMode == 0) {
        float* Cf = C + (long)bz * cB;
        #pragma unroll
        for (int mi = 0; mi < 4; mi++) {
            #pragma unroll
            for (int ni = 0; ni < 4; ni++) {
                long r = row0 + wm * 64 + mi * 16 + g;
                int  cc = col0 + wn * 32 + ni * 8 + 2 * t;
                float b0 = bias[cc], b1 = bias[cc + 1];
                *(float2*)&Cf[r * Ntot + cc]       = make_float2(acc[mi][ni][0] + b0, acc[mi][ni][1] + b1);
                *(float2*)&Cf[(r + 8) * Ntot + cc] = make_float2(acc[mi][ni][2] + b0, acc[mi][ni][3] + b1);
            }
        }
    } else if (outMode == 2) {
        __half* Ch = (__half*)C + (long)bz * cB;
        #pragma unroll
        for (int mi = 0; mi < 4; mi++) {
            #pragma unroll
            for (int ni = 0; ni < 4; ni++) {
                long r = row0 + wm * 64 + mi * 16 + g;
                int  cc = col0 + wn * 32 + ni * 8 + 2 * t;
                float b0 = bias[cc], b1 = bias[cc + 1];
                *(__half2*)&Ch[r * Ntot + cc]       = __floats2half2_rn(acc[mi][ni][0] + b0, acc[mi][ni][1] + b1);
                *(__half2*)&Ch[(r + 8) * Ntot + cc] = __floats2half2_rn(acc[mi][ni][2] + b0, acc[mi][ni][3] + b1);
            }
        }
    } else {
        // stage to smem [s][d] then write out[b][s][d] coalesced
        __syncthreads();
        float* Ts = (float*)smem;
        int b = (int)(row0 >> 10), d0 = (int)(row0 & 1023);
        #pragma unroll
        for (int mi = 0; mi < 4; mi++) {
            #pragma unroll
            for (int ni = 0; ni < 4; ni++) {
                int rl = wm * 64 + mi * 16 + g;
                int cl = wn * 32 + ni * 8 + 2 * t;
                float b0 = bias[col0 + cl], b1 = bias[col0 + cl + 1];
                Ts[cl * 129 + rl]           = acc[mi][ni][0] + b0;
                Ts[(cl + 1) * 129 + rl]     = acc[mi][ni][1] + b1;
                Ts[cl * 129 + rl + 8]       = acc[mi][ni][2] + b0;
                Ts[(cl + 1) * 129 + rl + 8] = acc[mi][ni][3] + b1;
            }
        }
        __syncthreads();
        #pragma unroll
        for (int j = 0; j < 16; j++) {
            int sl = j * 8 + (tid >> 5);
            int d4 = (tid & 31) * 4;
            float4 o = make_float4(Ts[sl * 129 + d4], Ts[sl * 129 + d4 + 1],
                                   Ts[sl * 129 + d4 + 2], Ts[sl * 129 + d4 + 3]);
            *(float4*)&C[((long)(b * SS + col0 + sl)) * DD + d0 + d4] = o;
        }
    }
}

// ---------------- positional attention via fp16 tensor cores ----------------
// Qs [128][72] fp16, Ks [256][72] fp16, Vt [64][266] fp16 (V transposed, pad 266)
#define PA_SMEM_BYTES ((128*72 + 256*72 + 64*266) * 2)
__global__ void __launch_bounds__(256) pos_attn_mma(const __half* __restrict__ qkv,
                                                    float* __restrict__ out)
{
    extern __shared__ __half smh[];
    __half* Qs = smh;                 // [128][72]
    __half* Ks = Qs + 128 * 72;       // [256][72]
    __half* Vt = Ks + 256 * 72;       // [64][266]
    int tid = threadIdx.x, lane = tid & 31, w = tid >> 5;
    int qt = blockIdx.x, bh = blockIdx.y;
    int b = bh >> 4, h = bh & 15;

    const __half* Qg = qkv + ((long)b * SS + qt * 128) * DD + h * DK;
    const __half* Kg = qkv + (long)BB*SS*DD + (long)b * SS * DD + h * DK;
    const __half* Vg = Kg + (long)BB*SS*DD;

    for (int idx = tid; idx < 128 * 8; idx += 256) {
        int r = idx >> 3, c = (idx & 7) * 8;
        *(uint4*)&Qs[r * 72 + c] = *(const uint4*)&Qg[(long)r * DD + c];
    }
    for (int idx = tid; idx < 256 * 8; idx += 256) {
        int r = idx >> 3, c = (idx & 7) * 8;
        *(uint4*)&Ks[r * 72 + c] = *(const uint4*)&Kg[(long)r * DD + c];
        uint4 vv = *(const uint4*)&Vg[(long)r * DD + c];
        const __half* vh = (const __half*)&vv;
        #pragma unroll
        for (int j = 0; j < 8; j++) Vt[(c + j) * 266 + r] = vh[j];
    }
    __syncthreads();

    int g = lane >> 2, tig = lane & 3;
    int row = w * 16 + g;

    unsigned qa[4][4];
    #pragma unroll
    for (int ks = 0; ks < 4; ks++) {
        const __half* qb = Qs + row * 72 + ks * 16 + 2 * tig;
        qa[ks][0] = *(const unsigned*)qb;
        qa[ks][1] = *(const unsigned*)(qb + 8 * 72);
        qa[ks][2] = *(const unsigned*)(qb + 8);
        qa[ks][3] = *(const unsigned*)(qb + 8 * 72 + 8);
    }

    float sc[32][4];
    #pragma unroll
    for (int nf = 0; nf < 32; nf++) {
        sc[nf][0] = sc[nf][1] = sc[nf][2] = sc[nf][3] = 0.f;
        const __half* kb = Ks + (nf * 8 + g) * 72 + 2 * tig;
        #pragma unroll
        for (int ks = 0; ks < 4; ks++) {
            unsigned bb[2];
            bb[0] = *(const unsigned*)(kb + ks * 16);
            bb[1] = *(const unsigned*)(kb + ks * 16 + 8);
            mma_f16(sc[nf], qa[ks], bb);
        }
    }

    float mx0 = -1e30f, mx1 = -1e30f;
    #pragma unroll
    for (int nf = 0; nf < 32; nf++) {
        mx0 = fmaxf(mx0, fmaxf(sc[nf][0], sc[nf][1]));
        mx1 = fmaxf(mx1, fmaxf(sc[nf][2], sc[nf][3]));
    }
    mx0 = fmaxf(mx0, __shfl_xor_sync(~0u, mx0, 1));
    mx0 = fmaxf(mx0, __shfl_xor_sync(~0u, mx0, 2));
    mx1 = fmaxf(mx1, __shfl_xor_sync(~0u, mx1, 1));
    mx1 = fmaxf(mx1, __shfl_xor_sync(~0u, mx1, 2));
    float sum0 = 0.f, sum1 = 0.f;
    #pragma unroll
    for (int nf = 0; nf < 32; nf++) {
        float p0 = __expf((sc[nf][0] - mx0) * 0.125f), p1 = __expf((sc[nf][1] - mx0) * 0.125f);
        float p2 = __expf((sc[nf][2] - mx1) * 0.125f), p3 = __expf((sc[nf][3] - mx1) * 0.125f);
        sum0 += p0 + p1; sum1 += p2 + p3;
        sc[nf][0] = p0; sc[nf][1] = p1; sc[nf][2] = p2; sc[nf][3] = p3;
    }
    sum0 += __shfl_xor_sync(~0u, sum0, 1); sum0 += __shfl_xor_sync(~0u, sum0, 2);
    sum1 += __shfl_xor_sync(~0u, sum1, 1); sum1 += __shfl_xor_sync(~0u, sum1, 2);

    #pragma unroll
    for (int ksi = 0; ksi < 16; ksi++) {
        unsigned p0 = packh2(sc[2*ksi][0],   sc[2*ksi][1]);
        unsigned p1 = packh2(sc[2*ksi][2],   sc[2*ksi][3]);
        unsigned p2 = packh2(sc[2*ksi+1][0], sc[2*ksi+1][1]);
        unsigned p3 = packh2(sc[2*ksi+1][2], sc[2*ksi+1][3]);
        unsigned* d = (unsigned*)sc[2*ksi];
        d[0] = p0; d[1] = p1; d[2] = p2; d[3] = p3;
    }

    float o[8][4];
    #pragma unroll
    for (int nf = 0; nf < 8; nf++) { o[nf][0]=o[nf][1]=o[nf][2]=o[nf][3]=0.f; }
    #pragma unroll
    for (int nf = 0; nf < 8; nf++) {
        const __half* vb = Vt + (nf * 8 + g) * 266 + 2 * tig;
        #pragma unroll
        for (int ksi = 0; ksi < 16; ksi++) {
            unsigned bb[2];
            bb[0] = *(const unsigned*)(vb + ksi * 16);
            bb[1] = *(const unsigned*)(vb + ksi * 16 + 8);
            mma_f16(o[nf], (const unsigned*)sc[2*ksi], bb);
        }
    }

    float inv0 = 1.f / sum0, inv1 = 1.f / sum1;
    long orow0 = ((long)b * SS + qt * 128 + row) * DD + h * DK;
    long orow1 = orow0 + 8L * DD;
    #pragma unroll
    for (int nf = 0; nf < 8; nf++) {
        int c = nf * 8 + 2 * tig;
        *(float2*)&out[orow0 + c] = make_float2(o[nf][0] * inv0, o[nf][1] * inv0);
        *(float2*)&out[orow1 + c] = make_float2(o[nf][2] * inv1, o[nf][3] * inv1);
    }
}

// ---------------- LayerNorm over sequence + transpose -> fp16 [B,D,S] ----------------
__global__ void __launch_bounds__(256) ln_c_kernel(const float* __restrict__ xin,
                                                   const float* __restrict__ ac,
                                                   const float* __restrict__ bcv,
                                                   __half* __restrict__ xo)
{
    __shared__ float tile[32][257];
    __shared__ float red[8][32], red2[8][32];
    __shared__ float s_mean[32], s_inv[32];
    int b = blockIdx.y, d0 = blockIdx.x * 32;
    int tid = threadIdx.x, lane = tid & 31, w = tid >> 5;
    const float* base = xin + (long)b * SS * DD + d0;
    #pragma unroll 4
    for (int i = 0; i < 32; i++) {
        int s = w * 32 + i;
        tile[lane][s] = base[(long)s * DD + lane];
    }
    __syncthreads();
    {
        int d = tid & 31, ch = tid >> 5;
        float s1 = 0.f, s2 = 0.f;
        #pragma unroll
        for (int j = 0; j < 32; j++) {
            float v = tile[d][ch * 32 + j]; s1 += v; s2 += v * v;
        }
        red[ch][d] = s1; red2[ch][d] = s2;
    }
    __syncthreads();
    if (tid < 32) {
        float s1 = 0.f, s2 = 0.f;
        #pragma unroll
        for (int ch = 0; ch < 8; ch++) { s1 += red[ch][tid]; s2 += red2[ch][tid]; }
        float mean = s1 * (1.f / SS);
        float var  = (s2 - s1 * mean) * (1.f / (SS - 1));
        s_mean[tid] = mean;
        s_inv[tid]  = 1.f / (sqrtf(var) + EPSV);
    }
    __syncthreads();
    {
        int d = tid >> 3, s0 = (tid & 7) * 32;
        float mean = s_mean[d], inv = s_inv[d];
        long dstBase = ((long)b * DD + d0 + d) * SS;
        #pragma unroll
        for (int j = 0; j < 32; j += 2) {
            int s = s0 + j;
            float v0 = ac[s+0] * (tile[d][s+0] - mean) * inv + bcv[s+0];
            float v1 = ac[s+1] * (tile[d][s+1] - mean) * inv + bcv[s+1];
            *(__half2*)&xo[dstBase + s] = __floats2half2_rn(v0, v1);
        }
    }
}

// ---------------- channel attention via fp16 tensor cores (flash, double-buffered) ----------------
// Qs [128][40]; K bufs 2x[128][40]; Vt bufs 2x[32][138] fp16
#define CA_SMEM_BYTES ((128*40 + 2*128*40 + 2*32*138) * 2)
__global__ void __launch_bounds__(256) chan_attn_mma(const __half* __restrict__ qkvc,
                                                     __half* __restrict__ xc)
{
    extern __shared__ __half smh[];
    __half* Qs = smh;                       // [128][40]
    __half* Kb0 = Qs + 128 * 40;            // [128][40]
    __half* Kb1 = Kb0 + 128 * 40;
    __half* Vb0 = Kb1 + 128 * 40;           // [32][138]
    __half* Vb1 = Vb0 + 32 * 138;
    int tid = threadIdx.x, lane = tid & 31, w = tid >> 5;
    int qt = blockIdx.x, bh = blockIdx.y;
    int b = bh >> 3, h = bh & 7;
    const float scale = 0.1767766952966369f;   // 1/sqrt(32)

    const long qBase = (long)b * DD * SS + h * SK;
    const long nStride = (long)BB * DD * SS;

    // per-thread K/V load coords (2 rows per thread)
    int lr0 = tid >> 2,          lc0 = (tid & 3) * 8;
    int lr1 = (tid + 256) >> 2,  lc1 = ((tid + 256) & 3) * 8;

    for (int idx = tid; idx < 128 * 4; idx += 256) {
        int r = idx >> 2, c = (idx & 3) * 8;
        *(uint4*)&Qs[r * 40 + c] = *(const uint4*)&qkvc[qBase + (long)(qt * 128 + r) * SS + c];
    }

    // preload st=0 into regs, store to buf 0
    uint4 kreg0, kreg1, vreg0, vreg1;
    kreg0 = *(const uint4*)&qkvc[qBase + nStride     + (long)lr0 * SS + lc0];
    kreg1 = *(const uint4*)&qkvc[qBase + nStride     + (long)lr1 * SS + lc1];
    vreg0 = *(const uint4*)&qkvc[qBase + 2 * nStride + (long)lr0 * SS + lc0];
    vreg1 = *(const uint4*)&qkvc[qBase + 2 * nStride + (long)lr1 * SS + lc1];
    {
        *(uint4*)&Kb0[lr0 * 40 + lc0] = kreg0;
        *(uint4*)&Kb0[lr1 * 40 + lc1] = kreg1;
        const __half* vh0 = (const __half*)&vreg0;
        const __half* vh1 = (const __half*)&vreg1;
        #pragma unroll
        for (int j = 0; j < 8; j++) Vb0[(lc0 + j) * 138 + lr0] = vh0[j];
        #pragma unroll
        for (int j = 0; j < 8; j++) Vb0[(lc1 + j) * 138 + lr1] = vh1[j];
    }
    __syncthreads();

    int g = lane >> 2, tig = lane & 3;
    int row = w * 16 + g;

    unsigned qa[2][4];
    #pragma unroll
    for (int ks = 0; ks < 2; ks++) {
        const __half* qb = Qs + row * 40 + ks * 16 + 2 * tig;
        qa[ks][0] = *(const unsigned*)qb;
        qa[ks][1] = *(const unsigned*)(qb + 8 * 40);
        qa[ks][2] = *(const unsigned*)(qb + 8);
        qa[ks][3] = *(const unsigned*)(qb + 8 * 40 + 8);
    }

    float m0 = -1e30f, m1 = -1e30f, l0 = 0.f, l1 = 0.f;
    float o[4][4];
    #pragma unroll
    for (int nf = 0; nf < 4; nf++) { o[nf][0]=o[nf][1]=o[nf][2]=o[nf][3]=0.f; }

    for (int st = 0; st < 8; st++) {
        // issue global loads for st+1 (overlap with compute below)
        if (st + 1 < 8) {
            long kRow = (long)((st + 1) * 128);
            kreg0 = *(const uint4*)&qkvc[qBase + nStride     + (kRow + lr0) * SS + lc0];
            kreg1 = *(const uint4*)&qkvc[qBase + nStride     + (kRow + lr1) * SS + lc1];
            vreg0 = *(const uint4*)&qkvc[qBase + 2 * nStride + (kRow + lr0) * SS + lc0];
            vreg1 = *(const uint4*)&qkvc[qBase + 2 * nStride + (kRow + lr1) * SS + lc1];
        }
        const __half* Ks = (st & 1) ? Kb1 : Kb0;
        const __half* Vt = (st & 1) ? Vb1 : Vb0;

        float sc[16][4];
        #pragma unroll
        for (int nf = 0; nf < 16; nf++) {
            sc[nf][0] = sc[nf][1] = sc[nf][2] = sc[nf][3] = 0.f;
            const __half* kb = Ks + (nf * 8 + g) * 40 + 2 * tig;
            #pragma unroll
            for (int ks = 0; ks < 2; ks++) {
                unsigned bb[2];
                bb[0] = *(const unsigned*)(kb + ks * 16);
                bb[1] = *(const unsigned*)(kb + ks * 16 + 8);
                mma_f16(sc[nf], qa[ks], bb);
            }
        }
        float tm0 = -1e30f, tm1 = -1e30f;
        #pragma unroll
        for (int nf = 0; nf < 16; nf++) {
            tm0 = fmaxf(tm0, fmaxf(sc[nf][0], sc[nf][1]));
            tm1 = fmaxf(tm1, fmaxf(sc[nf][2], sc[nf][3]));
        }
        tm0 = fmaxf(tm0, __shfl_xor_sync(~0u, tm0, 1));
        tm0 = fmaxf(tm0, __shfl_xor_sync(~0u, tm0, 2));
        tm1 = fmaxf(tm1, __shfl_xor_sync(~0u, tm1, 1));
        tm1 = fmaxf(tm1, __shfl_xor_sync(~0u, tm1, 2));
        float nm0 = fmaxf(m0, tm0), nm1 = fmaxf(m1, tm1);
        float al0 = __expf((m0 - nm0) * scale), al1 = __expf((m1 - nm1) * scale);
        m0 = nm0; m1 = nm1;
        float ts0 = 0.f, ts1 = 0.f;
        #pragma unroll
        for (int nf = 0; nf < 16; nf++) {
            float p0 = __expf((sc[nf][0] - nm0) * scale), p1 = __expf((sc[nf][1] - nm0) * scale);
            float p2 = __expf((sc[nf][2] - nm1) * scale), p3 = __expf((sc[nf][3] - nm1) * scale);
            ts0 += p0 + p1; ts1 += p2 + p3;
            sc[nf][0] = p0; sc[nf][1] = p1; sc[nf][2] = p2; sc[nf][3] = p3;
        }
        ts0 += __shfl_xor_sync(~0u, ts0, 1); ts0 += __shfl_xor_sync(~0u, ts0, 2);
        ts1 += __shfl_xor_sync(~0u, ts1, 1); ts1 += __shfl_xor_sync(~0u, ts1, 2);
        l0 = l0 * al0 + ts0; l1 = l1 * al1 + ts1;
        #pragma unroll
        for (int nf = 0; nf < 4; nf++) {
            o[nf][0] *= al0; o[nf][1] *= al0;
            o[nf][2] *= al1; o[nf][3] *= al1;
        }
        #pragma unroll
        for (int ksi = 0; ksi < 8; ksi++) {
            unsigned p0 = packh2(sc[2*ksi][0],   sc[2*ksi][1]);
            unsigned p1 = packh2(sc[2*ksi][2],   sc[2*ksi][3]);
            unsigned p2 = packh2(sc[2*ksi+1][0], sc[2*ksi+1][1]);
            unsigned p3 = packh2(sc[2*ksi+1][2], sc[2*ksi+1][3]);
            unsigned* d = (unsigned*)sc[2*ksi];
            d[0] = p0; d[1] = p1; d[2] = p2; d[3] = p3;
        }
        #pragma unroll
        for (int nf = 0; nf < 4; nf++) {
            const __half* vb = Vt + (nf * 8 + g) * 138 + 2 * tig;
            #pragma unroll
            for (int ksi = 0; ksi < 8; ksi++) {
                unsigned bb[2];
                bb[0] = *(const unsigned*)(vb + ksi * 16);
                bb[1] = *(const unsigned*)(vb + ksi * 16 + 8);
                mma_f16(o[nf], (const unsigned*)sc[2*ksi], bb);
            }
        }

        if (st + 1 < 8) {
            __syncthreads();   // all warps done reading buf (st+1)&1 from iter st-1
            __half* Kn = (st & 1) ? Kb0 : Kb1;
            __half* Vn = (st & 1) ? Vb0 : Vb1;
            *(uint4*)&Kn[lr0 * 40 + lc0] = kreg0;
            *(uint4*)&Kn[lr1 * 40 + lc1] = kreg1;
            const __half* vh0 = (const __half*)&vreg0;
            const __half* vh1 = (const __half*)&vreg1;
            #pragma unroll
            for (int j = 0; j < 8; j++) Vn[(lc0 + j) * 138 + lr0] = vh0[j];
            #pragma unroll
            for (int j = 0; j < 8; j++) Vn[(lc1 + j) * 138 + lr1] = vh1[j];
            __syncthreads();   // stores visible before next compute
        }
    }

    float inv0 = 1.f / l0, inv1 = 1.f / l1;
    long orow0 = ((long)b * DD + qt * 128 + row) * SS + h * SK;
    long orow1 = orow0 + 8L * SS;
    #pragma unroll
    for (int nf = 0; nf < 4; nf++) {
        int c = nf * 8 + 2 * tig;
        *(__half2*)&xc[orow0 + c] = __floats2half2_rn(o[nf][0] * inv0, o[nf][1] * inv0);
        *(__half2*)&xc[orow1 + c] = __floats2half2_rn(o[nf][2] * inv1, o[nf][3] * inv1);
    }
}

// ---------------- launch ----------------
extern "C" void kernel_launch(void* const* d_in, const int* in_sizes, int n_in,
                              void* d_out, int out_size)
{
    const float* x   = (const float*)d_in[0];
    const float* Wp  = (const float*)d_in[1];
    const float* bp  = (const float*)d_in[2];
    const float* Wc  = (const float*)d_in[3];
    const float* bc  = (const float*)d_in[4];
    const float* ap  = (const float*)d_in[5];
    const float* bpp = (const float*)d_in[6];
    const float* ac  = (const float*)d_in[7];
    const float* bcc = (const float*)d_in[8];
    float* out = (float*)d_out;

    void *p_xp, *p_qkv, *p_xp2, *p_xt, *p_qkvc, *p_xc;
    void *p_wph, *p_wpl, *p_wch, *p_wcl;
    cudaGetSymbolAddress(&p_xp, g_xp);
    cudaGetSymbolAddress(&p_qkv, g_qkv);
    cudaGetSymbolAddress(&p_xp2, g_xp2);
    cudaGetSymbolAddress(&p_xt, g_xt);
    cudaGetSymbolAddress(&p_qkvc, g_qkvc);
    cudaGetSymbolAddress(&p_xc, g_xc);
    cudaGetSymbolAddress(&p_wph, g_WpT_hi);
    cudaGetSymbolAddress(&p_wpl, g_WpT_lo);
    cudaGetSymbolAddress(&p_wch, g_WcT_hi);
    cudaGetSymbolAddress(&p_wcl, g_WcT_lo);
    __half* xp   = (__half*)p_xp;
    __half* qkv  = (__half*)p_qkv;
    float* xp2   = (float*)p_xp2;
    __half* xt   = (__half*)p_xt;
    __half* qkvc = (__half*)p_qkvc;
    __half* xc   = (__half*)p_xc;
    __half* WpTh = (__half*)p_wph;
    __half* WpTl = (__half*)p_wpl;
    __half* WcTh = (__half*)p_wch;
    __half* WcTl = (__half*)p_wcl;

    cudaFuncSetAttribute((const void*)pos_attn_mma,  cudaFuncAttributeMaxDynamicSharedMemorySize, PA_SMEM_BYTES);
    cudaFuncSetAttribute((const void*)chan_attn_mma, cudaFuncAttributeMaxDynamicSharedMemorySize, CA_SMEM_BYTES);
    cudaFuncSetAttribute((const void*)gemm_f16,      cudaFuncAttributeMaxDynamicSharedMemorySize, GEMM_SMEM_BYTES);

    // 0. transpose + fp16 hi/lo split of weights
    split_transpose<<<dim3(DD/32, DD/32, 3), 256>>>(Wp, WpTh, WpTl, DD, DD);
    split_transpose<<<dim3(SS/32, SS/32, 4), 256>>>(Wc, WcTh, WcTl, SS, SS);

    // 1. LayerNorm over D -> fp16
    ln_p_kernel<<<BB*SS, 256>>>(x, ap, bpp, xp);

    // 2. positional qkv (fp16, hi-only weights) -> fp16 qkv
    gemm_f16<<<dim3(DD/128, (BB*SS)/128, 3), 256, GEMM_SMEM_BYTES>>>(
        xp, WpTh, WpTl, bp, (float*)qkv, DD, DD,
        0L, (long)DD*DD, (long)DD, (long)BB*SS*DD, 2, 0);

    // 3. positional attention (fp16 tensor cores)
    pos_attn_mma<<<dim3(2, BB*HP), 256, PA_SMEM_BYTES>>>(qkv, xp2);

    // 4. LayerNorm over S + transpose -> fp16 [B,D,S]
    ln_c_kernel<<<dim3(DD/32, BB), 256>>>(xp2, ac, bcc, xt);

    // 5. channel qkv (fp16, hi-only weights) -> fp16 qkvc
    gemm_f16<<<dim3(SS/128, (BB*DD)/128, 3), 256, GEMM_SMEM_BYTES>>>(
        xt, WcTh, WcTl, bc, (float*)qkvc, SS, SS,
        0L, (long)SS*SS, (long)SS, (long)BB*DD*SS, 2, 0);

    // 6. channel attention (fp16 tensor cores, flash, double-buffered) -> fp16
    chan_attn_mma<<<dim3(8, BB*HC), 256, CA_SMEM_BYTES>>>(qkvc, xc);

    // 7. output projection (fp16 hi+lo compensated) with Wc[3], bc[3]; fused transpose -> out
    gemm_f16<<<dim3(SS/128, (BB*DD)/128, 1), 256, GEMM_SMEM_BYTES>>>(
        xc, WcTh + 3L*SS*SS, WcTl + 3L*SS*SS, bc + 3L*SS, out, SS, SS,
        0L, 0L, 0L, 0L, 1, 1);
}

// round 13
// speedup vs baseline: 1.1206x; 1.0575x over previous
#include <cuda_runtime.h>
#include <cuda_fp16.h>
#include <math.h>
#include <stdint.h>

// Problem constants
#define BB 16
#define SS 256
#define DD 1024
#define HP 16
#define DK 64
#define HC 8
#define SK 32
#define EPSV 1e-6f

// ---------------- scratch buffers (static device memory; no allocation) ----------------
__device__ __half g_xp[BB*SS*DD];        // LN_p output fp16 [B,S,D]
__device__ __half g_qkv[3*BB*SS*DD];     // pos qkv fp16      [3,B,S,D]
__device__ float  g_xp2[BB*SS*DD];       // pos attn out      [B,S,D]
__device__ __half g_xt[BB*DD*SS];        // LN_c out (transposed) fp16 [B,D,S]
__device__ __half g_qkvc[3*BB*DD*SS];    // channel qkv fp16  [3,B,D,S]
__device__ __half g_xc[BB*DD*SS];        // channel attn out fp16 [B,D,S]
__device__ __half g_WpT_hi[3*DD*DD];     // Wp transposed [N][K], fp16 hi
__device__ __half g_WpT_lo[3*DD*DD];     // fp16 lo (residual)
__device__ __half g_WcT_hi[4*SS*SS];
__device__ __half g_WcT_lo[4*SS*SS];

// ---------------- helpers ----------------
__device__ __forceinline__ void cp_async16(uint32_t smem, const void* g) {
    asm volatile("cp.async.cg.shared.global [%0], [%1], 16;" :: "r"(smem), "l"(g));
}

__device__ __forceinline__ void mma_f16(float* c, const unsigned* a, const unsigned* b) {
    asm volatile("mma.sync.aligned.m16n8k16.row.col.f32.f16.f16.f32 "
        "{%0,%1,%2,%3}, {%4,%5,%6,%7}, {%8,%9}, {%0,%1,%2,%3};"
        : "+f"(c[0]), "+f"(c[1]), "+f"(c[2]), "+f"(c[3])
        : "r"(a[0]), "r"(a[1]), "r"(a[2]), "r"(a[3]), "r"(b[0]), "r"(b[1]));
}

#define LDM4(r, addr) \
    asm volatile("ldmatrix.sync.aligned.m8n8.x4.shared.b16 {%0,%1,%2,%3}, [%4];" \
        : "=r"((r)[0]), "=r"((r)[1]), "=r"((r)[2]), "=r"((r)[3]) : "r"(addr))

__device__ __forceinline__ uint32_t smem_u32(const void* p) {
    uint32_t a;
    asm("{ .reg .u64 t; cvta.to.shared.u64 t, %1; cvt.u32.u64 %0, t; }" : "=r"(a) : "l"(p));
    return a;
}

__device__ __forceinline__ unsigned packh2(float x, float y) {
    __half2 h = __floats2half2_rn(x, y);
    return *(unsigned*)&h;
}

// ---------------- weight transpose + fp16 hi/lo split ----------------
__global__ void __launch_bounds__(256) split_transpose(const float* __restrict__ W,
                                                       __half* __restrict__ hi,
                                                       __half* __restrict__ lo,
                                                       int K, int N)
{
    __shared__ float t[32][33];
    int bz = blockIdx.z;
    W  += (long)bz * K * N;
    hi += (long)bz * K * N;
    lo += (long)bz * K * N;
    int n0 = blockIdx.x * 32, k0 = blockIdx.y * 32;
    int tx = threadIdx.x & 31, ty = threadIdx.x >> 5;
    #pragma unroll
    for (int j = 0; j < 32; j += 8)
        t[ty + j][tx] = W[(long)(k0 + ty + j) * N + n0 + tx];
    __syncthreads();
    #pragma unroll
    for (int j = 0; j < 32; j += 8) {
        float v = t[tx][ty + j];
        __half h = __float2half_rn(v);
        __half l = __float2half_rn(v - __half2float(h));
        long o = (long)(n0 + ty + j) * K + k0 + tx;
        hi[o] = h; lo[o] = l;
    }
}

// ---------------- LayerNorm over channels -> fp16 ----------------
__global__ void __launch_bounds__(256) ln_p_kernel(const float* __restrict__ x,
                                                   const float* __restrict__ ap,
                                                   const float* __restrict__ bp,
                                                   __half* __restrict__ xo)
{
    long row = blockIdx.x;
    const float* xr = x + row * DD;
    int tid = threadIdx.x;
    float s = 0.f, s2 = 0.f;
    #pragma unroll
    for (int i = tid; i < DD; i += 256) { float v = xr[i]; s += v; s2 += v*v; }
    __shared__ float rs[8], rs2[8];
    #pragma unroll
    for (int o = 16; o; o >>= 1) { s += __shfl_xor_sync(~0u, s, o); s2 += __shfl_xor_sync(~0u, s2, o); }
    if ((tid & 31) == 0) { rs[tid>>5] = s; rs2[tid>>5] = s2; }
    __syncthreads();
    s = 0.f; s2 = 0.f;
    #pragma unroll
    for (int w = 0; w < 8; w++) { s += rs[w]; s2 += rs2[w]; }
    float mean = s * (1.f / DD);
    float var  = (s2 - s * mean) * (1.f / (DD - 1));
    float inv  = 1.f / (sqrtf(var) + EPSV);
    #pragma unroll
    for (int i = tid; i < DD; i += 256) {
        float v = xr[i];
        xo[row * DD + i] = __float2half_rn(ap[i] * (v - mean) * inv + bp[i]);
    }
}

// ---------------- fp16 tensor GEMM: C = A * Bhi^T (+ Blo^T) + bias ----------------
// 2-stage cp.async pipeline, BK=64. A [M][K] fp16, Bh/Bl [N][K] fp16 (K-major).
// BM=128 BN=128, 256 threads, warp grid 2(M) x 4(N), warp tile 64x32.
// smem rows stride 72 halfs (144 B, conflict-free ldmatrix).
// outMode: 0=fp32 C, 1=fp32 fused transpose, 2=fp16 C. compLo: add A*Blo^T term.
#define GA_TILE 18432            // 128 x 72 halfs
#define G_STAGE (3 * GA_TILE)    // A + Bh + Bl = 55296
#define GEMM_SMEM_BYTES (2 * G_STAGE)   // 110592; transpose buffer (66048) fits

__device__ __forceinline__ void gemm_load_chunk(
    uint32_t sbase,
    const __half* __restrict__ A,
    const __half* __restrict__ Bh, const __half* __restrict__ Bl,
    long row0, int col0, int K, int k0, int buf, int tid, int compLo)
{
    uint32_t base = sbase + buf * G_STAGE;
    #pragma unroll
    for (int i = 0; i < 4; i++) {
        int idx = tid + i * 256;
        int r = idx >> 3, sgi = idx & 7;
        uint32_t d = base + (uint32_t)(r * 144 + sgi * 16);
        long aoff = (row0 + r) * (long)K + k0 + sgi * 8;
        long boff = (long)(col0 + r) * K + k0 + sgi * 8;
        cp_async16(d,            &A[aoff]);
        cp_async16(d + GA_TILE,  &Bh[boff]);
        if (compLo) cp_async16(d + 2*GA_TILE, &Bl[boff]);
    }
    asm volatile("cp.async.commit_group;");
}

__global__ void __launch_bounds__(256, 2) gemm_f16(const __half* __restrict__ A,
                                                   const __half* __restrict__ Bh,
                                                   const __half* __restrict__ Bl,
                                                   const float* __restrict__ bias,
                                                   float* __restrict__ C,
                                                   int K, int Ntot,
                                                   long aB, long bB, long biasB, long cB,
                                                   int outMode, int compLo)
{
    extern __shared__ char smem[];
    uint32_t sbase = smem_u32(smem);
    int tid  = threadIdx.x;
    int warp = tid >> 5, lane = tid & 31;
    int wm = warp & 1, wn = warp >> 1;        // 2 x 4 warp grid, tile 64M x 32N
    int g = lane >> 2, t = lane & 3;
    int bz = blockIdx.z;
    A    += (long)bz * aB;
    Bh   += (long)bz * bB;
    Bl   += (long)bz * bB;
    bias += (long)bz * biasB;
    long row0 = (long)blockIdx.y * 128;
    int  col0 = blockIdx.x * 128;

    uint32_t aAddr = sbase +
        (uint32_t)(((wm * 64 + (lane & 7) + ((lane >> 3) & 1) * 8) * 72 + (lane >> 4) * 8) * 2);
    uint32_t bAddr = sbase + GA_TILE +
        (uint32_t)(((wn * 32 + (lane & 7) + ((lane >> 4) & 1) * 8) * 72 + ((lane >> 3) & 1) * 8) * 2);

    float acc[4][4][4];
    #pragma unroll
    for (int mi = 0; mi < 4; mi++)
        #pragma unroll
        for (int ni = 0; ni < 4; ni++)
            #pragma unroll
            for (int r = 0; r < 4; r++) acc[mi][ni][r] = 0.f;

    int NC = K >> 6;
    gemm_load_chunk(sbase, A, Bh, Bl, row0, col0, K, 0, 0, tid, compLo);

    for (int c = 0; c < NC; c++) {
        int buf = c & 1;
        asm volatile("cp.async.wait_group 0;" ::: "memory");
        __syncthreads();
        if (c + 1 < NC)
            gemm_load_chunk(sbase, A, Bh, Bl, row0, col0, K, (c + 1) << 6, buf ^ 1, tid, compLo);

        uint32_t bo = buf * G_STAGE;
        #pragma unroll
        for (int ks = 0; ks < 4; ks++) {
            uint32_t ak = aAddr + bo + ks * 32;
            uint32_t bk = bAddr + bo + ks * 32;
            unsigned af[4][4];
            LDM4(af[0], ak);
            LDM4(af[1], ak + 2304);
            LDM4(af[2], ak + 4608);
            LDM4(af[3], ak + 6912);
            unsigned bhf[2][4];
            LDM4(bhf[0], bk);
            LDM4(bhf[1], bk + 2304);
            #pragma unroll
            for (int mi = 0; mi < 4; mi++)
                #pragma unroll
                for (int ni = 0; ni < 4; ni++)
                    mma_f16(acc[mi][ni], af[mi], &bhf[ni >> 1][(ni & 1) * 2]);
            if (compLo) {
                unsigned blf[2][4];
                LDM4(blf[0], bk + GA_TILE);
                LDM4(blf[1], bk + GA_TILE + 2304);
                #pragma unroll
                for (int mi = 0; mi < 4; mi++)
                    #pragma unroll
                    for (int ni = 0; ni < 4; ni++)
                        mma_f16(acc[mi][ni], af[mi], &blf[ni >> 1][(ni & 1) * 2]);
            }
        }
    }

    if (outMode == 0) {
        float* Cf = C + (long)bz * cB;
        #pragma unroll
        for (int mi = 0; mi < 4; mi++) {
            #pragma unroll
            for (int ni = 0; ni < 4; ni++) {
                long r = row0 + wm * 64 + mi * 16 + g;
                int  cc = col0 + wn * 32 + ni * 8 + 2 * t;
                float b0 = bias[cc], b1 = bias[cc + 1];
                *(float2*)&Cf[r * Ntot + cc]       = make_float2(acc[mi][ni][0] + b0, acc[mi][ni][1] + b1);
                *(float2*)&Cf[(r + 8) * Ntot + cc] = make_float2(acc[mi][ni][2] + b0, acc[mi][ni][3] + b1);
            }
        }
    } else if (outMode == 2) {
        __half* Ch = (__half*)C + (long)bz * cB;
        #pragma unroll
        for (int mi = 0; mi < 4; mi++) {
            #pragma unroll
            for (int ni = 0; ni < 4; ni++) {
                long r = row0 + wm * 64 + mi * 16 + g;
                int  cc = col0 + wn * 32 + ni * 8 + 2 * t;
                float b0 = bias[cc], b1 = bias[cc + 1];
                *(__half2*)&Ch[r * Ntot + cc]       = __floats2half2_rn(acc[mi][ni][0] + b0, acc[mi][ni][1] + b1);
                *(__half2*)&Ch[(r + 8) * Ntot + cc] = __floats2half2_rn(acc[mi][ni][2] + b0, acc[mi][ni][3] + b1);
            }
        }
    } else {
        // stage to smem [s][d] then write out[b][s][d] coalesced
        __syncthreads();
        float* Ts = (float*)smem;
        int b = (int)(row0 >> 10), d0 = (int)(row0 & 1023);
        #pragma unroll
        for (int mi = 0; mi < 4; mi++) {
            #pragma unroll
            for (int ni = 0; ni < 4; ni++) {
                int rl = wm * 64 + mi * 16 + g;
                int cl = wn * 32 + ni * 8 + 2 * t;
                float b0 = bias[col0 + cl], b1 = bias[col0 + cl + 1];
                Ts[cl * 129 + rl]           = acc[mi][ni][0] + b0;
                Ts[(cl + 1) * 129 + rl]     = acc[mi][ni][1] + b1;
                Ts[cl * 129 + rl + 8]       = acc[mi][ni][2] + b0;
                Ts[(cl + 1) * 129 + rl + 8] = acc[mi][ni][3] + b1;
            }
        }
        __syncthreads();
        #pragma unroll
        for (int j = 0; j < 16; j++) {
            int sl = j * 8 + (tid >> 5);
            int d4 = (tid & 31) * 4;
            float4 o = make_float4(Ts[sl * 129 + d4], Ts[sl * 129 + d4 + 1],
                                   Ts[sl * 129 + d4 + 2], Ts[sl * 129 + d4 + 3]);
            *(float4*)&C[((long)(b * SS + col0 + sl)) * DD + d0 + d4] = o;
        }
    }
}

// ---------------- positional attention via fp16 tensor cores ----------------
// Qs [128][72] fp16, Ks [256][72] fp16, Vt [64][266] fp16 (V transposed, pad 266)
#define PA_SMEM_BYTES ((128*72 + 256*72 + 64*266) * 2)
__global__ void __launch_bounds__(256) pos_attn_mma(const __half* __restrict__ qkv,
                                                    float* __restrict__ out)
{
    extern __shared__ __half smh[];
    __half* Qs = smh;                 // [128][72]
    __half* Ks = Qs + 128 * 72;       // [256][72]
    __half* Vt = Ks + 256 * 72;       // [64][266]
    int tid = threadIdx.x, lane = tid & 31, w = tid >> 5;
    int qt = blockIdx.x, bh = blockIdx.y;
    int b = bh >> 4, h = bh & 15;

    const __half* Qg = qkv + ((long)b * SS + qt * 128) * DD + h * DK;
    const __half* Kg = qkv + (long)BB*SS*DD + (long)b * SS * DD + h * DK;
    const __half* Vg = Kg + (long)BB*SS*DD;

    for (int idx = tid; idx < 128 * 8; idx += 256) {
        int r = idx >> 3, c = (idx & 7) * 8;
        *(uint4*)&Qs[r * 72 + c] = *(const uint4*)&Qg[(long)r * DD + c];
    }
    for (int idx = tid; idx < 256 * 8; idx += 256) {
        int r = idx >> 3, c = (idx & 7) * 8;
        *(uint4*)&Ks[r * 72 + c] = *(const uint4*)&Kg[(long)r * DD + c];
        uint4 vv = *(const uint4*)&Vg[(long)r * DD + c];
        const __half* vh = (const __half*)&vv;
        #pragma unroll
        for (int j = 0; j < 8; j++) Vt[(c + j) * 266 + r] = vh[j];
    }
    __syncthreads();

    int g = lane >> 2, tig = lane & 3;
    int row = w * 16 + g;

    unsigned qa[4][4];
    #pragma unroll
    for (int ks = 0; ks < 4; ks++) {
        const __half* qb = Qs + row * 72 + ks * 16 + 2 * tig;
        qa[ks][0] = *(const unsigned*)qb;
        qa[ks][1] = *(const unsigned*)(qb + 8 * 72);
        qa[ks][2] = *(const unsigned*)(qb + 8);
        qa[ks][3] = *(const unsigned*)(qb + 8 * 72 + 8);
    }

    float sc[32][4];
    #pragma unroll
    for (int nf = 0; nf < 32; nf++) {
        sc[nf][0] = sc[nf][1] = sc[nf][2] = sc[nf][3] = 0.f;
        const __half* kb = Ks + (nf * 8 + g) * 72 + 2 * tig;
        #pragma unroll
        for (int ks = 0; ks < 4; ks++) {
            unsigned bb[2];
            bb[0] = *(const unsigned*)(kb + ks * 16);
            bb[1] = *(const unsigned*)(kb + ks * 16 + 8);
            mma_f16(sc[nf], qa[ks], bb);
        }
    }

    float mx0 = -1e30f, mx1 = -1e30f;
    #pragma unroll
    for (int nf = 0; nf < 32; nf++) {
        mx0 = fmaxf(mx0, fmaxf(sc[nf][0], sc[nf][1]));
        mx1 = fmaxf(mx1, fmaxf(sc[nf][2], sc[nf][3]));
    }
    mx0 = fmaxf(mx0, __shfl_xor_sync(~0u, mx0, 1));
    mx0 = fmaxf(mx0, __shfl_xor_sync(~0u, mx0, 2));
    mx1 = fmaxf(mx1, __shfl_xor_sync(~0u, mx1, 1));
    mx1 = fmaxf(mx1, __shfl_xor_sync(~0u, mx1, 2));
    float sum0 = 0.f, sum1 = 0.f;
    #pragma unroll
    for (int nf = 0; nf < 32; nf++) {
        float p0 = __expf((sc[nf][0] - mx0) * 0.125f), p1 = __expf((sc[nf][1] - mx0) * 0.125f);
        float p2 = __expf((sc[nf][2] - mx1) * 0.125f), p3 = __expf((sc[nf][3] - mx1) * 0.125f);
        sum0 += p0 + p1; sum1 += p2 + p3;
        sc[nf][0] = p0; sc[nf][1] = p1; sc[nf][2] = p2; sc[nf][3] = p3;
    }
    sum0 += __shfl_xor_sync(~0u, sum0, 1); sum0 += __shfl_xor_sync(~0u, sum0, 2);
    sum1 += __shfl_xor_sync(~0u, sum1, 1); sum1 += __shfl_xor_sync(~0u, sum1, 2);

    #pragma unroll
    for (int ksi = 0; ksi < 16; ksi++) {
        unsigned p0 = packh2(sc[2*ksi][0],   sc[2*ksi][1]);
        unsigned p1 = packh2(sc[2*ksi][2],   sc[2*ksi][3]);
        unsigned p2 = packh2(sc[2*ksi+1][0], sc[2*ksi+1][1]);
        unsigned p3 = packh2(sc[2*ksi+1][2], sc[2*ksi+1][3]);
        unsigned* d = (unsigned*)sc[2*ksi];
        d[0] = p0; d[1] = p1; d[2] = p2; d[3] = p3;
    }

    float o[8][4];
    #pragma unroll
    for (int nf = 0; nf < 8; nf++) { o[nf][0]=o[nf][1]=o[nf][2]=o[nf][3]=0.f; }
    #pragma unroll
    for (int nf = 0; nf < 8; nf++) {
        const __half* vb = Vt + (nf * 8 + g) * 266 + 2 * tig;
        #pragma unroll
        for (int ksi = 0; ksi < 16; ksi++) {
            unsigned bb[2];
            bb[0] = *(const unsigned*)(vb + ksi * 16);
            bb[1] = *(const unsigned*)(vb + ksi * 16 + 8);
            mma_f16(o[nf], (const unsigned*)sc[2*ksi], bb);
        }
    }

    float inv0 = 1.f / sum0, inv1 = 1.f / sum1;
    long orow0 = ((long)b * SS + qt * 128 + row) * DD + h * DK;
    long orow1 = orow0 + 8L * DD;
    #pragma unroll
    for (int nf = 0; nf < 8; nf++) {
        int c = nf * 8 + 2 * tig;
        *(float2*)&out[orow0 + c] = make_float2(o[nf][0] * inv0, o[nf][1] * inv0);
        *(float2*)&out[orow1 + c] = make_float2(o[nf][2] * inv1, o[nf][3] * inv1);
    }
}

// ---------------- LayerNorm over sequence + transpose -> fp16 [B,D,S] ----------------
__global__ void __launch_bounds__(256) ln_c_kernel(const float* __restrict__ xin,
                                                   const float* __restrict__ ac,
                                                   const float* __restrict__ bcv,
                                                   __half* __restrict__ xo)
{
    __shared__ float tile[32][257];
    __shared__ float red[8][32], red2[8][32];
    __shared__ float s_mean[32], s_inv[32];
    int b = blockIdx.y, d0 = blockIdx.x * 32;
    int tid = threadIdx.x, lane = tid & 31, w = tid >> 5;
    const float* base = xin + (long)b * SS * DD + d0;
    #pragma unroll 4
    for (int i = 0; i < 32; i++) {
        int s = w * 32 + i;
        tile[lane][s] = base[(long)s * DD + lane];
    }
    __syncthreads();
    {
        int d = tid & 31, ch = tid >> 5;
        float s1 = 0.f, s2 = 0.f;
        #pragma unroll
        for (int j = 0; j < 32; j++) {
            float v = tile[d][ch * 32 + j]; s1 += v; s2 += v * v;
        }
        red[ch][d] = s1; red2[ch][d] = s2;
    }
    __syncthreads();
    if (tid < 32) {
        float s1 = 0.f, s2 = 0.f;
        #pragma unroll
        for (int ch = 0; ch < 8; ch++) { s1 += red[ch][tid]; s2 += red2[ch][tid]; }
        float mean = s1 * (1.f / SS);
        float var  = (s2 - s1 * mean) * (1.f / (SS - 1));
        s_mean[tid] = mean;
        s_inv[tid]  = 1.f / (sqrtf(var) + EPSV);
    }
    __syncthreads();
    {
        int d = tid >> 3, s0 = (tid & 7) * 32;
        float mean = s_mean[d], inv = s_inv[d];
        long dstBase = ((long)b * DD + d0 + d) * SS;
        #pragma unroll
        for (int j = 0; j < 32; j += 2) {
            int s = s0 + j;
            float v0 = ac[s+0] * (tile[d][s+0] - mean) * inv + bcv[s+0];
            float v1 = ac[s+1] * (tile[d][s+1] - mean) * inv + bcv[s+1];
            *(__half2*)&xo[dstBase + s] = __floats2half2_rn(v0, v1);
        }
    }
}

// ---------------- channel attention via fp16 tensor cores (flash, double-buffered) ----------------
// Qs [128][40]; K bufs 2x[128][40]; Vt bufs 2x[32][138] fp16
#define CA_SMEM_BYTES ((128*40 + 2*128*40 + 2*32*138) * 2)
__global__ void __launch_bounds__(256) chan_attn_mma(const __half* __restrict__ qkvc,
                                                     __half* __restrict__ xc)
{
    extern __shared__ __half smh[];
    __half* Qs = smh;                       // [128][40]
    __half* Kb0 = Qs + 128 * 40;            // [128][40]
    __half* Kb1 = Kb0 + 128 * 40;
    __half* Vb0 = Kb1 + 128 * 40;           // [32][138]
    __half* Vb1 = Vb0 + 32 * 138;
    int tid = threadIdx.x, lane = tid & 31, w = tid >> 5;
    int qt = blockIdx.x, bh = blockIdx.y;
    int b = bh >> 3, h = bh & 7;
    const float scale = 0.1767766952966369f;   // 1/sqrt(32)

    const long qBase = (long)b * DD * SS + h * SK;
    const long nStride = (long)BB * DD * SS;

    int lr0 = tid >> 2,          lc0 = (tid & 3) * 8;
    int lr1 = (tid + 256) >> 2,  lc1 = ((tid + 256) & 3) * 8;

    for (int idx = tid; idx < 128 * 4; idx += 256) {
        int r = idx >> 2, c = (idx & 3) * 8;
        *(uint4*)&Qs[r * 40 + c] = *(const uint4*)&qkvc[qBase + (long)(qt * 128 + r) * SS + c];
    }

    uint4 kreg0, kreg1, vreg0, vreg1;
    kreg0 = *(const uint4*)&qkvc[qBase + nStride     + (long)lr0 * SS + lc0];
    kreg1 = *(const uint4*)&qkvc[qBase + nStride     + (long)lr1 * SS + lc1];
    vreg0 = *(const uint4*)&qkvc[qBase + 2 * nStride + (long)lr0 * SS + lc0];
    vreg1 = *(const uint4*)&qkvc[qBase + 2 * nStride + (long)lr1 * SS + lc1];
    {
        *(uint4*)&Kb0[lr0 * 40 + lc0] = kreg0;
        *(uint4*)&Kb0[lr1 * 40 + lc1] = kreg1;
        const __half* vh0 = (const __half*)&vreg0;
        const __half* vh1 = (const __half*)&vreg1;
        #pragma unroll
        for (int j = 0; j < 8; j++) Vb0[(lc0 + j) * 138 + lr0] = vh0[j];
        #pragma unroll
        for (int j = 0; j < 8; j++) Vb0[(lc1 + j) * 138 + lr1] = vh1[j];
    }
    __syncthreads();

    int g = lane >> 2, tig = lane & 3;
    int row = w * 16 + g;

    unsigned qa[2][4];
    #pragma unroll
    for (int ks = 0; ks < 2; ks++) {
        const __half* qb = Qs + row * 40 + ks * 16 + 2 * tig;
        qa[ks][0] = *(const unsigned*)qb;
        qa[ks][1] = *(const unsigned*)(qb + 8 * 40);
        qa[ks][2] = *(const unsigned*)(qb + 8);
        qa[ks][3] = *(const unsigned*)(qb + 8 * 40 + 8);
    }

    float m0 = -1e30f, m1 = -1e30f, l0 = 0.f, l1 = 0.f;
    float o[4][4];
    #pragma unroll
    for (int nf = 0; nf < 4; nf++) { o[nf][0]=o[nf][1]=o[nf][2]=o[nf][3]=0.f; }

    for (int st = 0; st < 8; st++) {
        if (st + 1 < 8) {
            long kRow = (long)((st + 1) * 128);
            kreg0 = *(const uint4*)&qkvc[qBase + nStride     + (kRow + lr0) * SS + lc0];
            kreg1 = *(const uint4*)&qkvc[qBase + nStride     + (kRow + lr1) * SS + lc1];
            vreg0 = *(const uint4*)&qkvc[qBase + 2 * nStride + (kRow + lr0) * SS + lc0];
            vreg1 = *(const uint4*)&qkvc[qBase + 2 * nStride + (kRow + lr1) * SS + lc1];
        }
        const __half* Ks = (st & 1) ? Kb1 : Kb0;
        const __half* Vt = (st & 1) ? Vb1 : Vb0;

        float sc[16][4];
        #pragma unroll
        for (int nf = 0; nf < 16; nf++) {
            sc[nf][0] = sc[nf][1] = sc[nf][2] = sc[nf][3] = 0.f;
            const __half* kb = Ks + (nf * 8 + g) * 40 + 2 * tig;
            #pragma unroll
            for (int ks = 0; ks < 2; ks++) {
                unsigned bb[2];
                bb[0] = *(const unsigned*)(kb + ks * 16);
                bb[1] = *(const unsigned*)(kb + ks * 16 + 8);
                mma_f16(sc[nf], qa[ks], bb);
            }
        }
        float tm0 = -1e30f, tm1 = -1e30f;
        #pragma unroll
        for (int nf = 0; nf < 16; nf++) {
            tm0 = fmaxf(tm0, fmaxf(sc[nf][0], sc[nf][1]));
            tm1 = fmaxf(tm1, fmaxf(sc[nf][2], sc[nf][3]));
        }
        tm0 = fmaxf(tm0, __shfl_xor_sync(~0u, tm0, 1));
        tm0 = fmaxf(tm0, __shfl_xor_sync(~0u, tm0, 2));
        tm1 = fmaxf(tm1, __shfl_xor_sync(~0u, tm1, 1));
        tm1 = fmaxf(tm1, __shfl_xor_sync(~0u, tm1, 2));
        float nm0 = fmaxf(m0, tm0), nm1 = fmaxf(m1, tm1);
        float al0 = __expf((m0 - nm0) * scale), al1 = __expf((m1 - nm1) * scale);
        m0 = nm0; m1 = nm1;
        float ts0 = 0.f, ts1 = 0.f;
        #pragma unroll
        for (int nf = 0; nf < 16; nf++) {
            float p0 = __expf((sc[nf][0] - nm0) * scale), p1 = __expf((sc[nf][1] - nm0) * scale);
            float p2 = __expf((sc[nf][2] - nm1) * scale), p3 = __expf((sc[nf][3] - nm1) * scale);
            ts0 += p0 + p1; ts1 += p2 + p3;
            sc[nf][0] = p0; sc[nf][1] = p1; sc[nf][2] = p2; sc[nf][3] = p3;
        }
        ts0 += __shfl_xor_sync(~0u, ts0, 1); ts0 += __shfl_xor_sync(~0u, ts0, 2);
        ts1 += __shfl_xor_sync(~0u, ts1, 1); ts1 += __shfl_xor_sync(~0u, ts1, 2);
        l0 = l0 * al0 + ts0; l1 = l1 * al1 + ts1;
        #pragma unroll
        for (int nf = 0; nf < 4; nf++) {
            o[nf][0] *= al0; o[nf][1] *= al0;
            o[nf][2] *= al1; o[nf][3] *= al1;
        }
        #pragma unroll
        for (int ksi = 0; ksi < 8; ksi++) {
            unsigned p0 = packh2(sc[2*ksi][0],   sc[2*ksi][1]);
            unsigned p1 = packh2(sc[2*ksi][2],   sc[2*ksi][3]);
            unsigned p2 = packh2(sc[2*ksi+1][0], sc[2*ksi+1][1]);
            unsigned p3 = packh2(sc[2*ksi+1][2], sc[2*ksi+1][3]);
            unsigned* d = (unsigned*)sc[2*ksi];
            d[0] = p0; d[1] = p1; d[2] = p2; d[3] = p3;
        }
        #pragma unroll
        for (int nf = 0; nf < 4; nf++) {
            const __half* vb = Vt + (nf * 8 + g) * 138 + 2 * tig;
            #pragma unroll
            for (int ksi = 0; ksi < 8; ksi++) {
                unsigned bb[2];
                bb[0] = *(const unsigned*)(vb + ksi * 16);
                bb[1] = *(const unsigned*)(vb + ksi * 16 + 8);
                mma_f16(o[nf], (const unsigned*)sc[2*ksi], bb);
            }
        }

        if (st + 1 < 8) {
            __syncthreads();
            __half* Kn = (st & 1) ? Kb0 : Kb1;
            __half* Vn = (st & 1) ? Vb0 : Vb1;
            *(uint4*)&Kn[lr0 * 40 + lc0] = kreg0;
            *(uint4*)&Kn[lr1 * 40 + lc1] = kreg1;
            const __half* vh0 = (const __half*)&vreg0;
            const __half* vh1 = (const __half*)&vreg1;
            #pragma unroll
            for (int j = 0; j < 8; j++) Vn[(lc0 + j) * 138 + lr0] = vh0[j];
            #pragma unroll
            for (int j = 0; j < 8; j++) Vn[(lc1 + j) * 138 + lr1] = vh1[j];
            __syncthreads();
        }
    }

    float inv0 = 1.f / l0, inv1 = 1.f / l1;
    long orow0 = ((long)b * DD + qt * 128 + row) * SS + h * SK;
    long orow1 = orow0 + 8L * SS;
    #pragma unroll
    for (int nf = 0; nf < 4; nf++) {
        int c = nf * 8 + 2 * tig;
        *(__half2*)&xc[orow0 + c] = __floats2half2_rn(o[nf][0] * inv0, o[nf][1] * inv0);
        *(__half2*)&xc[orow1 + c] = __floats2half2_rn(o[nf][2] * inv1, o[nf][3] * inv1);
    }
}

// ---------------- launch ----------------
extern "C" void kernel_launch(void* const* d_in, const int* in_sizes, int n_in,
                              void* d_out, int out_size)
{
    const float* x   = (const float*)d_in[0];
    const float* Wp  = (const float*)d_in[1];
    const float* bp  = (const float*)d_in[2];
    const float* Wc  = (const float*)d_in[3];
    const float* bc  = (const float*)d_in[4];
    const float* ap  = (const float*)d_in[5];
    const float* bpp = (const float*)d_in[6];
    const float* ac  = (const float*)d_in[7];
    const float* bcc = (const float*)d_in[8];
    float* out = (float*)d_out;

    void *p_xp, *p_qkv, *p_xp2, *p_xt, *p_qkvc, *p_xc;
    void *p_wph, *p_wpl, *p_wch, *p_wcl;
    cudaGetSymbolAddress(&p_xp, g_xp);
    cudaGetSymbolAddress(&p_qkv, g_qkv);
    cudaGetSymbolAddress(&p_xp2, g_xp2);
    cudaGetSymbolAddress(&p_xt, g_xt);
    cudaGetSymbolAddress(&p_qkvc, g_qkvc);
    cudaGetSymbolAddress(&p_xc, g_xc);
    cudaGetSymbolAddress(&p_wph, g_WpT_hi);
    cudaGetSymbolAddress(&p_wpl, g_WpT_lo);
    cudaGetSymbolAddress(&p_wch, g_WcT_hi);
    cudaGetSymbolAddress(&p_wcl, g_WcT_lo);
    __half* xp   = (__half*)p_xp;
    __half* qkv  = (__half*)p_qkv;
    float* xp2   = (float*)p_xp2;
    __half* xt   = (__half*)p_xt;
    __half* qkvc = (__half*)p_qkvc;
    __half* xc   = (__half*)p_xc;
    __half* WpTh = (__half*)p_wph;
    __half* WpTl = (__half*)p_wpl;
    __half* WcTh = (__half*)p_wch;
    __half* WcTl = (__half*)p_wcl;

    cudaFuncSetAttribute((const void*)pos_attn_mma,  cudaFuncAttributeMaxDynamicSharedMemorySize, PA_SMEM_BYTES);
    cudaFuncSetAttribute((const void*)chan_attn_mma, cudaFuncAttributeMaxDynamicSharedMemorySize, CA_SMEM_BYTES);
    cudaFuncSetAttribute((const void*)gemm_f16,      cudaFuncAttributeMaxDynamicSharedMemorySize, GEMM_SMEM_BYTES);

    // 0. transpose + fp16 hi/lo split of weights
    split_transpose<<<dim3(DD/32, DD/32, 3), 256>>>(Wp, WpTh, WpTl, DD, DD);
    split_transpose<<<dim3(SS/32, SS/32, 4), 256>>>(Wc, WcTh, WcTl, SS, SS);

    // 1. LayerNorm over D -> fp16
    ln_p_kernel<<<BB*SS, 256>>>(x, ap, bpp, xp);

    // 2. positional qkv (fp16, hi-only weights) -> fp16 qkv
    gemm_f16<<<dim3(DD/128, (BB*SS)/128, 3), 256, GEMM_SMEM_BYTES>>>(
        xp, WpTh, WpTl, bp, (float*)qkv, DD, DD,
        0L, (long)DD*DD, (long)DD, (long)BB*SS*DD, 2, 0);

    // 3. positional attention (fp16 tensor cores)
    pos_attn_mma<<<dim3(2, BB*HP), 256, PA_SMEM_BYTES>>>(qkv, xp2);

    // 4. LayerNorm over S + transpose -> fp16 [B,D,S]
    ln_c_kernel<<<dim3(DD/32, BB), 256>>>(xp2, ac, bcc, xt);

    // 5. channel qkv (fp16, hi-only weights) -> fp16 qkvc
    gemm_f16<<<dim3(SS/128, (BB*DD)/128, 3), 256, GEMM_SMEM_BYTES>>>(
        xt, WcTh, WcTl, bc, (float*)qkvc, SS, SS,
        0L, (long)SS*SS, (long)SS, (long)BB*DD*SS, 2, 0);

    // 6. channel attention (fp16 tensor cores, flash, double-buffered) -> fp16
    chan_attn_mma<<<dim3(8, BB*HC), 256, CA_SMEM_BYTES>>>(qkvc, xc);

    // 7. output projection (fp16 hi+lo compensated) with Wc[3], bc[3]; fused transpose -> out
    gemm_f16<<<dim3(SS/128, (BB*DD)/128, 1), 256, GEMM_SMEM_BYTES>>>(
        xc, WcTh + 3L*SS*SS, WcTl + 3L*SS*SS, bc + 3L*SS, out, SS, SS,
        0L, 0L, 0L, 0L, 1, 1);
}